// round 8
// baseline (speedup 1.0000x reference)
#include <cuda_runtime.h>
#include <cuda_bf16.h>
#include <math.h>
#include <stdint.h>

#define BATCH   2
#define SEQ     2048
#define DMODEL  1024
#define NHEAD   16
#define DHEAD   64
#define BT      (BATCH * SEQ)
#define NQT     (SEQ / 128)

// Scratch (device globals). All hold tf32-rounded fp32.
__device__ float g_q[BT * DMODEL];
__device__ float g_k[BT * DMODEL];
__device__ float g_v[BT * DMODEL];
__device__ float g_attn[BT * DMODEL];
__device__ float g_xc[BT * DMODEL];
__device__ float g_w4[4 * DMODEL * DMODEL];

__device__ __forceinline__ uint32_t f2tf(float f) {
    uint32_t u;
    asm("cvt.rna.tf32.f32 %0, %1;" : "=r"(u) : "f"(f));
    return u;
}

__device__ __forceinline__ uint32_t smem_u32(const void* p) {
    uint32_t a;
    asm("{ .reg .u64 t; cvta.to.shared.u64 t, %1; cvt.u32.u64 %0, t; }" : "=r"(a) : "l"(p));
    return a;
}

__device__ __forceinline__ void mma_tf32(float c[4], const uint32_t a[4], const uint32_t b[2]) {
    asm volatile(
        "mma.sync.aligned.m16n8k8.row.col.f32.tf32.tf32.f32 "
        "{%0,%1,%2,%3}, {%4,%5,%6,%7}, {%8,%9}, {%0,%1,%2,%3};"
        : "+f"(c[0]), "+f"(c[1]), "+f"(c[2]), "+f"(c[3])
        : "r"(a[0]), "r"(a[1]), "r"(a[2]), "r"(a[3]), "r"(b[0]), "r"(b[1]));
}

__device__ __forceinline__ void cp16(uint32_t dst, const void* src) {
    asm volatile("cp.async.cg.shared.global [%0], [%1], 16;" :: "r"(dst), "l"(src));
}
__device__ __forceinline__ void cp_commit() {
    asm volatile("cp.async.commit_group;");
}
__device__ __forceinline__ void cp_wait2() {
    asm volatile("cp.async.wait_group 2;");
}
__device__ __forceinline__ void cp_wait1() {
    asm volatile("cp.async.wait_group 1;");
}
__device__ __forceinline__ void cp_wait0() {
    asm volatile("cp.async.wait_group 0;");
}

// ---------------------------------------------------------------------------
// Prepass: round X and the four weights to tf32 once.
// ---------------------------------------------------------------------------
__global__ void cvt_kernel(const float* __restrict__ X,
                           const float* __restrict__ Wq,
                           const float* __restrict__ Wk,
                           const float* __restrict__ Wv,
                           const float* __restrict__ Wo)
{
    const int y = blockIdx.y;
    const float* src;
    float* dst;
    int n;
    if (y == 0)      { src = X;  dst = g_xc;                          n = BT * DMODEL; }
    else             { src = (y == 1) ? Wq : (y == 2) ? Wk : (y == 3) ? Wv : Wo;
                       dst = g_w4 + (size_t)(y - 1) * DMODEL * DMODEL; n = DMODEL * DMODEL; }
    const int i = (blockIdx.x * 256 + threadIdx.x) * 4;
    if (i < n) {
        float4 v = *(const float4*)(src + i);
        uint4 u;
        u.x = f2tf(v.x); u.y = f2tf(v.y); u.z = f2tf(v.z); u.w = f2tf(v.w);
        *(uint4*)(dst + i) = u;
    }
}

// ---------------------------------------------------------------------------
// TF32 tensor-core GEMM: C[m,n] = sum_k A[m,k]*B[n,k]; inputs pre-tf32.
// CTA tile 128x64, 8 warps (4m x 2n), warp tile 32x32 (acc 16 regs).
// K-stage 16, 4-stage cp.async, one __syncthreads per k-step.
// 3 CTAs/SM (smem 60KB, regs capped by __launch_bounds__(256,3)).
// ---------------------------------------------------------------------------
#define GSTG_B   15360u                  // bytes/stage: A 10240 + B 5120
#define GSTG_F   3840                    // floats/stage
#define GEMM_DSM (4 * 15360)             // 61440

__device__ __forceinline__ void gemm_tc(const float* __restrict__ A,
                                        const float* __restrict__ B,
                                        float* __restrict__ C,
                                        int rope, const int* __restrict__ pos,
                                        int tfout)
{
    extern __shared__ float dsm[];
    const uint32_t sb = smem_u32(dsm);

    const int tid  = threadIdx.x;
    const int warp = tid >> 5, lane = tid & 31;
    const int wm = warp >> 1, wn = warp & 1;       // 4 x 2 warp grid
    const int g  = lane >> 2, qd = lane & 3;
    const int mbase = blockIdx.y * 128;
    const int nbase = blockIdx.x * 64;

    // producers: A 2 float4/thread, B 1 float4/thread
    const int ar = tid >> 1, ak = (tid & 1) * 8;
    const float* Arow = A + (size_t)(mbase + ar) * DMODEL + ak;
    const uint32_t aOff = (uint32_t)ar * 80u + (uint32_t)ak * 4u;
    const int br = tid >> 2, bk = (tid & 3) * 4;
    const float* Brow = B + (size_t)(nbase + br) * DMODEL + bk;
    const uint32_t bOff = 10240u + (uint32_t)br * 80u + (uint32_t)bk * 4u;

    float acc[2][4][4];
#pragma unroll
    for (int i = 0; i < 2; i++)
#pragma unroll
        for (int j = 0; j < 4; j++)
#pragma unroll
            for (int k = 0; k < 4; k++) acc[i][j][k] = 0.0f;

    // prologue: stages 0..2
#pragma unroll
    for (int s = 0; s < 3; s++) {
        const uint32_t base = sb + (uint32_t)s * GSTG_B;
        cp16(base + aOff,      Arow + s * 16);
        cp16(base + aOff + 16, Arow + s * 16 + 4);
        cp16(base + bOff,      Brow + s * 16);
        cp_commit();
    }

    const int NK = DMODEL / 16;   // 64
    for (int kt = 0; kt < NK; kt++) {
        cp_wait2();
        __syncthreads();

        if (kt + 3 < NK) {
            const int s = kt + 3;
            const uint32_t base = sb + (uint32_t)(s & 3) * GSTG_B;
            cp16(base + aOff,      Arow + s * 16);
            cp16(base + aOff + 16, Arow + s * 16 + 4);
            cp16(base + bOff,      Brow + s * 16);
        }
        cp_commit();

        const uint32_t* Ast = (const uint32_t*)(dsm + (kt & 3) * GSTG_F);
        const uint32_t* Bst = Ast + 2560;
#pragma unroll
        for (int ks = 0; ks < 2; ks++) {
            uint32_t af[2][4], bf[4][2];
#pragma unroll
            for (int mf = 0; mf < 2; mf++) {
                const uint32_t* p = &Ast[(wm * 32 + mf * 16 + g) * 20 + ks * 8 + qd];
                af[mf][0] = p[0];
                af[mf][1] = p[160];
                af[mf][2] = p[4];
                af[mf][3] = p[164];
            }
#pragma unroll
            for (int nf = 0; nf < 4; nf++) {
                const uint32_t* p = &Bst[(wn * 32 + nf * 8 + g) * 20 + ks * 8 + qd];
                bf[nf][0] = p[0];
                bf[nf][1] = p[4];
            }
#pragma unroll
            for (int mf = 0; mf < 2; mf++)
#pragma unroll
                for (int nf = 0; nf < 4; nf++)
                    mma_tf32(acc[mf][nf], af[mf], bf[nf]);
        }
    }

    // epilogue (optional fused RoPE; optional tf32 rounding of stores)
#pragma unroll
    for (int mf = 0; mf < 2; mf++) {
        const int r0 = mbase + wm * 32 + mf * 16 + g;
        const int r1 = r0 + 8;
        float p0 = 0.0f, p1 = 0.0f;
        if (rope) {
            p0 = (float)pos[r0 & (SEQ - 1)];
            p1 = (float)pos[r1 & (SEQ - 1)];
        }
#pragma unroll
        for (int nf = 0; nf < 4; nf++) {
            const int col = nbase + wn * 32 + nf * 8 + 2 * qd;
            float a0 = acc[mf][nf][0], a1 = acc[mf][nf][1];
            float a2 = acc[mf][nf][2], a3 = acc[mf][nf][3];
            if (rope) {
                const int j = (col >> 1) & 31;
                const float inv = exp2f((float)j * -0.41524101186092029f);
                float s0, c0, s1, c1;
                sincosf(p0 * inv, &s0, &c0);
                sincosf(p1 * inv, &s1, &c1);
                float n0 = a0 * c0 - a1 * s0;
                float n1 = a0 * s0 + a1 * c0;
                float n2 = a2 * c1 - a3 * s1;
                float n3 = a2 * s1 + a3 * c1;
                a0 = n0; a1 = n1; a2 = n2; a3 = n3;
            }
            if (tfout) {
                a0 = __uint_as_float(f2tf(a0));
                a1 = __uint_as_float(f2tf(a1));
                a2 = __uint_as_float(f2tf(a2));
                a3 = __uint_as_float(f2tf(a3));
            }
            *(float2*)&C[(size_t)r0 * DMODEL + col] = make_float2(a0, a1);
            *(float2*)&C[(size_t)r1 * DMODEL + col] = make_float2(a2, a3);
        }
    }
}

__global__ void __launch_bounds__(256, 3) qkv_kernel(const int* __restrict__ pos)
{
    const int z = blockIdx.z;
    const float* W = g_w4 + (size_t)z * DMODEL * DMODEL;
    float* dst = (z == 0) ? g_q : (z == 1) ? g_k : g_v;
    gemm_tc(g_xc, W, dst, z < 2 ? 1 : 0, pos, 1);
}

__global__ void __launch_bounds__(256, 3) proj_kernel(float* __restrict__ out)
{
    gemm_tc(g_attn, g_w4 + (size_t)3 * DMODEL * DMODEL, out, 0, (const int*)0, 0);
}

// ---------------------------------------------------------------------------
// Causal flash attention, tf32 warp MMA.
// 3-stage cp.async pipeline, ONE __syncthreads per key tile.
// 256 threads / 128 queries per q-tile, key tiles of 64; CTA does the
// q-tile pair (p, NQT-1-p) -> uniform 34 tile-units per CTA.
// Diagonal tiles bound the nf (QK) and s (PV) loops by the causal limit.
// ---------------------------------------------------------------------------
#define ATTN_STAGE 35840
#define ATTN_DSM   (3 * ATTN_STAGE)

__device__ __forceinline__ void attn_qtile(int qt, int b, int h,
                                           char* asm_s, uint32_t sb)
{
    const int tid = threadIdx.x, warp = tid >> 5, lane = tid & 31;
    const int g = lane >> 2, qd = lane & 3;

    const int r0 = qt * 128 + warp * 16 + g;
    const int r1 = r0 + 8;
    const int wrow_lo = qt * 128 + warp * 16;
    const int wrow_hi = wrow_lo + 15;

    uint32_t qa[8][4];
    const float* q0p = g_q + ((size_t)(b * SEQ + r0)) * DMODEL + h * DHEAD;
    const float* q1p = g_q + ((size_t)(b * SEQ + r1)) * DMODEL + h * DHEAD;
#pragma unroll
    for (int s = 0; s < 8; s++) {
        qa[s][0] = __float_as_uint(q0p[s * 8 + qd]     * 0.125f);
        qa[s][1] = __float_as_uint(q1p[s * 8 + qd]     * 0.125f);
        qa[s][2] = __float_as_uint(q0p[s * 8 + qd + 4] * 0.125f);
        qa[s][3] = __float_as_uint(q1p[s * 8 + qd + 4] * 0.125f);
    }

    float oacc[8][4];
#pragma unroll
    for (int i = 0; i < 8; i++)
#pragma unroll
        for (int k = 0; k < 4; k++) oacc[i][k] = 0.0f;
    float m0 = -1e30f, m1 = -1e30f, l0 = 0.0f, l1 = 0.0f;

    const int lrow = tid >> 2;
    const int lc   = (tid & 3) * 16;
    const int ntiles = 2 * qt + 2;
    const size_t gstep = (size_t)(b * SEQ + lrow) * DMODEL + h * DHEAD + lc;

    // issue K/V tile t into stage t%3
    auto issue_tile = [&](int t) {
        const float* kp = g_k + gstep + (size_t)t * 64 * DMODEL;
        const float* vp = g_v + gstep + (size_t)t * 64 * DMODEL;
        const uint32_t st = sb + (uint32_t)(t % 3) * ATTN_STAGE;
        const uint32_t ka = st + (uint32_t)(lrow * 68 + lc) * 4u;
        const uint32_t va = st + 17408u + (uint32_t)(lrow * 72 + lc) * 4u;
#pragma unroll
        for (int i = 0; i < 4; i++) {
            cp16(ka + i * 16, kp + i * 4);
            cp16(va + i * 16, vp + i * 4);
        }
    };

    issue_tile(0);
    cp_commit();

    for (int kt = 0; kt < ntiles; kt++) {
        if (kt + 1 < ntiles) issue_tile(kt + 1);   // stage (kt+1)%3 == (kt-2)%3: drained
        cp_commit();
        cp_wait1();            // tile kt's copies (this thread) complete
        __syncthreads();       // all threads' copies visible; frees stage for kt+2's issue

        const int kbase = kt * 64;
        if (kbase <= wrow_hi) {
            const uint32_t* Ks = (const uint32_t*)(asm_s + (kt % 3) * ATTN_STAGE);
            const uint32_t* Vs = (const uint32_t*)(asm_s + (kt % 3) * ATTN_STAGE + 17408);
            const bool needmask = (kbase + 63 > wrow_lo);
            const int lim = needmask ? ((wrow_hi - kbase) >> 3) : 7;   // last live 8-col group

            float sacc[8][4];
#pragma unroll
            for (int nf = 0; nf < 8; nf++) {
                if (nf <= lim) {
                    sacc[nf][0] = sacc[nf][1] = sacc[nf][2] = sacc[nf][3] = 0.0f;
#pragma unroll
                    for (int s = 0; s < 8; s++) {
                        uint32_t bf[2];
                        const uint32_t* kb = &Ks[(nf * 8 + g) * 68 + s * 8 + qd];
                        bf[0] = kb[0];
                        bf[1] = kb[4];
                        mma_tf32(sacc[nf], qa[s], bf);
                    }
                } else {
                    sacc[nf][0] = sacc[nf][1] = sacc[nf][2] = sacc[nf][3] = -1e30f;
                }
            }

            if (needmask) {
#pragma unroll
                for (int nf = 0; nf < 8; nf++) {
                    const int c0 = kbase + nf * 8 + 2 * qd;
                    if (c0 > r0)     sacc[nf][0] = -1e30f;
                    if (c0 + 1 > r0) sacc[nf][1] = -1e30f;
                    if (c0 > r1)     sacc[nf][2] = -1e30f;
                    if (c0 + 1 > r1) sacc[nf][3] = -1e30f;
                }
            }

            float mx0 = -1e30f, mx1 = -1e30f;
#pragma unroll
            for (int nf = 0; nf < 8; nf++) {
                mx0 = fmaxf(mx0, fmaxf(sacc[nf][0], sacc[nf][1]));
                mx1 = fmaxf(mx1, fmaxf(sacc[nf][2], sacc[nf][3]));
            }
            mx0 = fmaxf(mx0, __shfl_xor_sync(0xffffffffu, mx0, 1));
            mx0 = fmaxf(mx0, __shfl_xor_sync(0xffffffffu, mx0, 2));
            mx1 = fmaxf(mx1, __shfl_xor_sync(0xffffffffu, mx1, 1));
            mx1 = fmaxf(mx1, __shfl_xor_sync(0xffffffffu, mx1, 2));

            const float mn0 = fmaxf(m0, mx0), mn1 = fmaxf(m1, mx1);
            const float cr0 = __expf(m0 - mn0), cr1 = __expf(m1 - mn1);
            float sum0 = 0.0f, sum1 = 0.0f;
#pragma unroll
            for (int nf = 0; nf < 8; nf++) {
                sacc[nf][0] = __expf(sacc[nf][0] - mn0);
                sacc[nf][1] = __expf(sacc[nf][1] - mn0);
                sacc[nf][2] = __expf(sacc[nf][2] - mn1);
                sacc[nf][3] = __expf(sacc[nf][3] - mn1);
                sum0 += sacc[nf][0] + sacc[nf][1];
                sum1 += sacc[nf][2] + sacc[nf][3];
            }
            sum0 += __shfl_xor_sync(0xffffffffu, sum0, 1);
            sum0 += __shfl_xor_sync(0xffffffffu, sum0, 2);
            sum1 += __shfl_xor_sync(0xffffffffu, sum1, 1);
            sum1 += __shfl_xor_sync(0xffffffffu, sum1, 2);
            l0 = l0 * cr0 + sum0;
            l1 = l1 * cr1 + sum1;
            m0 = mn0; m1 = mn1;
#pragma unroll
            for (int nf = 0; nf < 8; nf++) {
                oacc[nf][0] *= cr0; oacc[nf][1] *= cr0;
                oacc[nf][2] *= cr1; oacc[nf][3] *= cr1;
            }

            const int src0 = (lane & 0x1c) | (qd >> 1);
            const int src1 = src0 + 2;
            const bool odd = (qd & 1);
#pragma unroll
            for (int s = 0; s < 8; s++) {
                if (s > lim) continue;    // all P in this key group are zero
                const float A0 = sacc[s][0], A1 = sacc[s][1];
                const float A2 = sacc[s][2], A3 = sacc[s][3];
                const float x0 = __shfl_sync(0xffffffffu, A0, src0);
                const float x1 = __shfl_sync(0xffffffffu, A1, src0);
                const float y0 = __shfl_sync(0xffffffffu, A2, src0);
                const float y1 = __shfl_sync(0xffffffffu, A3, src0);
                const float z0 = __shfl_sync(0xffffffffu, A0, src1);
                const float z1 = __shfl_sync(0xffffffffu, A1, src1);
                const float w0 = __shfl_sync(0xffffffffu, A2, src1);
                const float w1 = __shfl_sync(0xffffffffu, A3, src1);
                uint32_t af[4];
                af[0] = f2tf(odd ? x1 : x0);
                af[1] = f2tf(odd ? y1 : y0);
                af[2] = f2tf(odd ? z1 : z0);
                af[3] = f2tf(odd ? w1 : w0);
#pragma unroll
                for (int nf = 0; nf < 8; nf++) {
                    uint32_t bf[2];
                    const uint32_t* vb = &Vs[(s * 8 + qd) * 72 + nf * 8 + g];
                    bf[0] = vb[0];
                    bf[1] = vb[4 * 72];
                    mma_tf32(oacc[nf], af, bf);
                }
            }
        }
    }

    cp_wait0();   // drain pipeline state before the next q-tile reuses stages

    const float il0 = 1.0f / l0, il1 = 1.0f / l1;
    float* o0 = g_attn + ((size_t)(b * SEQ + r0)) * DMODEL + h * DHEAD;
    float* o1 = g_attn + ((size_t)(b * SEQ + r1)) * DMODEL + h * DHEAD;
#pragma unroll
    for (int nf = 0; nf < 8; nf++) {
        const int c = nf * 8 + 2 * qd;
        float2 v0, v1;
        v0.x = __uint_as_float(f2tf(oacc[nf][0] * il0));
        v0.y = __uint_as_float(f2tf(oacc[nf][1] * il0));
        v1.x = __uint_as_float(f2tf(oacc[nf][2] * il1));
        v1.y = __uint_as_float(f2tf(oacc[nf][3] * il1));
        *(float2*)&o0[c] = v0;
        *(float2*)&o1[c] = v1;
    }
}

__global__ void __launch_bounds__(256) attn_kernel()
{
    extern __shared__ char asm_s[];
    const uint32_t sb = smem_u32(asm_s);
    const int b = blockIdx.z, h = blockIdx.y;

    attn_qtile(NQT - 1 - blockIdx.x, b, h, asm_s, sb);   // heavy tile
    __syncthreads();
    attn_qtile(blockIdx.x, b, h, asm_s, sb);             // light tile
}

// ---------------------------------------------------------------------------
extern "C" void kernel_launch(void* const* d_in, const int* in_sizes, int n_in,
                              void* d_out, int out_size)
{
    const float* X  = (const float*)d_in[0];
    const float* Wq = (const float*)d_in[1];
    const float* Wk = (const float*)d_in[2];
    const float* Wv = (const float*)d_in[3];
    const float* Wo = (const float*)d_in[4];
    const int*  pos = (const int*)d_in[5];

    cudaFuncSetAttribute(qkv_kernel,  cudaFuncAttributeMaxDynamicSharedMemorySize, GEMM_DSM);
    cudaFuncSetAttribute(proj_kernel, cudaFuncAttributeMaxDynamicSharedMemorySize, GEMM_DSM);
    cudaFuncSetAttribute(attn_kernel, cudaFuncAttributeMaxDynamicSharedMemorySize, ATTN_DSM);

    cvt_kernel<<<dim3(4096, 5), 256>>>(X, Wq, Wk, Wv, Wo);
    qkv_kernel<<<dim3(DMODEL / 64, BT / 128, 3), 256, GEMM_DSM>>>(pos);
    attn_kernel<<<dim3(NQT / 2, NHEAD, BATCH), 256, ATTN_DSM>>>();
    proj_kernel<<<dim3(DMODEL / 64, BT / 128, 1), 256, GEMM_DSM>>>((float*)d_out);
}

// round 9
// speedup vs baseline: 1.0387x; 1.0387x over previous
#include <cuda_runtime.h>
#include <cuda_bf16.h>
#include <math.h>
#include <stdint.h>

#define BATCH   2
#define SEQ     2048
#define DMODEL  1024
#define NHEAD   16
#define DHEAD   64
#define BT      (BATCH * SEQ)
#define NQT     (SEQ / 128)

// Scratch (device globals). All hold tf32-rounded fp32.
__device__ float g_q[BT * DMODEL];
__device__ float g_k[BT * DMODEL];
__device__ float g_v[BT * DMODEL];
__device__ float g_attn[BT * DMODEL];
__device__ float g_xc[BT * DMODEL];
__device__ float g_w4[4 * DMODEL * DMODEL];

__device__ __forceinline__ uint32_t f2tf(float f) {
    uint32_t u;
    asm("cvt.rna.tf32.f32 %0, %1;" : "=r"(u) : "f"(f));
    return u;
}

__device__ __forceinline__ uint32_t smem_u32(const void* p) {
    uint32_t a;
    asm("{ .reg .u64 t; cvta.to.shared.u64 t, %1; cvt.u32.u64 %0, t; }" : "=r"(a) : "l"(p));
    return a;
}

__device__ __forceinline__ void mma_tf32(float c[4], const uint32_t a[4], const uint32_t b[2]) {
    asm volatile(
        "mma.sync.aligned.m16n8k8.row.col.f32.tf32.tf32.f32 "
        "{%0,%1,%2,%3}, {%4,%5,%6,%7}, {%8,%9}, {%0,%1,%2,%3};"
        : "+f"(c[0]), "+f"(c[1]), "+f"(c[2]), "+f"(c[3])
        : "r"(a[0]), "r"(a[1]), "r"(a[2]), "r"(a[3]), "r"(b[0]), "r"(b[1]));
}

__device__ __forceinline__ void cp16(uint32_t dst, const void* src) {
    asm volatile("cp.async.cg.shared.global [%0], [%1], 16;" :: "r"(dst), "l"(src));
}
__device__ __forceinline__ void cp_commit() {
    asm volatile("cp.async.commit_group;");
}
__device__ __forceinline__ void cp_wait2() {
    asm volatile("cp.async.wait_group 2;");
}
__device__ __forceinline__ void cp_wait1() {
    asm volatile("cp.async.wait_group 1;");
}
__device__ __forceinline__ void cp_wait0() {
    asm volatile("cp.async.wait_group 0;");
}

// ---------------------------------------------------------------------------
// Prepass: round X and the four weights to tf32 once.
// ---------------------------------------------------------------------------
__global__ void cvt_kernel(const float* __restrict__ X,
                           const float* __restrict__ Wq,
                           const float* __restrict__ Wk,
                           const float* __restrict__ Wv,
                           const float* __restrict__ Wo)
{
    const int y = blockIdx.y;
    const float* src;
    float* dst;
    int n;
    if (y == 0)      { src = X;  dst = g_xc;                          n = BT * DMODEL; }
    else             { src = (y == 1) ? Wq : (y == 2) ? Wk : (y == 3) ? Wv : Wo;
                       dst = g_w4 + (size_t)(y - 1) * DMODEL * DMODEL; n = DMODEL * DMODEL; }
    const int i = (blockIdx.x * 256 + threadIdx.x) * 4;
    if (i < n) {
        float4 v = *(const float4*)(src + i);
        uint4 u;
        u.x = f2tf(v.x); u.y = f2tf(v.y); u.z = f2tf(v.z); u.w = f2tf(v.w);
        *(uint4*)(dst + i) = u;
    }
}

// ---------------------------------------------------------------------------
// TF32 tensor-core GEMM (best measured config, R6): C[m,n] = sum_k A[m,k]*B[n,k]
// Block 128x128, 8 warps (2x4), warp tile 64x32, K-stage 16, 4-stage cp.async,
// one __syncthreads per k-step. Smem row stride 20 words (conflict-free).
// ---------------------------------------------------------------------------
#define GEMM_DSM 81920

__device__ __forceinline__ void gemm_tc(const float* __restrict__ A,
                                        const float* __restrict__ B,
                                        float* __restrict__ C,
                                        int rope, const int* __restrict__ pos,
                                        int tfout)
{
    extern __shared__ float dsm[];
    const uint32_t sb = smem_u32(dsm);

    const int tid  = threadIdx.x;
    const int warp = tid >> 5, lane = tid & 31;
    const int wm = warp >> 2, wn = warp & 3;
    const int g  = lane >> 2, qd = lane & 3;
    const int mbase = blockIdx.y * 128;
    const int nbase = blockIdx.x * 128;

    const int r  = tid >> 1;
    const int cq = (tid & 1) * 2;
    const float* Arow = A + (size_t)(mbase + r) * DMODEL + cq * 4;
    const float* Brow = B + (size_t)(nbase + r) * DMODEL + cq * 4;
    const uint32_t dOff = (uint32_t)r * 80u + (uint32_t)cq * 16u;

    float acc[4][4][4];
#pragma unroll
    for (int i = 0; i < 4; i++)
#pragma unroll
        for (int j = 0; j < 4; j++)
#pragma unroll
            for (int k = 0; k < 4; k++) acc[i][j][k] = 0.0f;

#pragma unroll
    for (int s = 0; s < 3; s++) {
        const uint32_t da = sb + (uint32_t)s * 10240u + dOff;
        const uint32_t db = da + 40960u;
        cp16(da,      Arow + s * 16);
        cp16(da + 16, Arow + s * 16 + 4);
        cp16(db,      Brow + s * 16);
        cp16(db + 16, Brow + s * 16 + 4);
        cp_commit();
    }

    const int NK = DMODEL / 16;   // 64
    for (int kt = 0; kt < NK; kt++) {
        cp_wait2();
        __syncthreads();

        if (kt + 3 < NK) {
            const int s = kt + 3;
            const uint32_t da = sb + (uint32_t)(s & 3) * 10240u + dOff;
            const uint32_t db = da + 40960u;
            cp16(da,      Arow + s * 16);
            cp16(da + 16, Arow + s * 16 + 4);
            cp16(db,      Brow + s * 16);
            cp16(db + 16, Brow + s * 16 + 4);
        }
        cp_commit();

        const uint32_t* Ast = (const uint32_t*)(dsm + (kt & 3) * 2560);
        const uint32_t* Bst = (const uint32_t*)(dsm + 10240 + (kt & 3) * 2560);
#pragma unroll
        for (int ks = 0; ks < 2; ks++) {
            uint32_t af[4][4], bf[4][2];
#pragma unroll
            for (int mf = 0; mf < 4; mf++) {
                const uint32_t* p = &Ast[(wm * 64 + mf * 16 + g) * 20 + ks * 8 + qd];
                af[mf][0] = p[0];
                af[mf][1] = p[160];
                af[mf][2] = p[4];
                af[mf][3] = p[164];
            }
#pragma unroll
            for (int nf = 0; nf < 4; nf++) {
                const uint32_t* p = &Bst[(wn * 32 + nf * 8 + g) * 20 + ks * 8 + qd];
                bf[nf][0] = p[0];
                bf[nf][1] = p[4];
            }
#pragma unroll
            for (int mf = 0; mf < 4; mf++)
#pragma unroll
                for (int nf = 0; nf < 4; nf++)
                    mma_tf32(acc[mf][nf], af[mf], bf[nf]);
        }
    }

    // epilogue (optional fused RoPE; optional tf32 rounding of stores)
#pragma unroll
    for (int mf = 0; mf < 4; mf++) {
        const int r0 = mbase + wm * 64 + mf * 16 + g;
        const int r1 = r0 + 8;
        float p0 = 0.0f, p1 = 0.0f;
        if (rope) {
            p0 = (float)pos[r0 & (SEQ - 1)];
            p1 = (float)pos[r1 & (SEQ - 1)];
        }
#pragma unroll
        for (int nf = 0; nf < 4; nf++) {
            const int col = nbase + wn * 32 + nf * 8 + 2 * qd;
            float a0 = acc[mf][nf][0], a1 = acc[mf][nf][1];
            float a2 = acc[mf][nf][2], a3 = acc[mf][nf][3];
            if (rope) {
                const int j = (col >> 1) & 31;
                const float inv = exp2f((float)j * -0.41524101186092029f);
                float s0, c0, s1, c1;
                sincosf(p0 * inv, &s0, &c0);
                sincosf(p1 * inv, &s1, &c1);
                float n0 = a0 * c0 - a1 * s0;
                float n1 = a0 * s0 + a1 * c0;
                float n2 = a2 * c1 - a3 * s1;
                float n3 = a2 * s1 + a3 * c1;
                a0 = n0; a1 = n1; a2 = n2; a3 = n3;
            }
            if (tfout) {
                a0 = __uint_as_float(f2tf(a0));
                a1 = __uint_as_float(f2tf(a1));
                a2 = __uint_as_float(f2tf(a2));
                a3 = __uint_as_float(f2tf(a3));
            }
            *(float2*)&C[(size_t)r0 * DMODEL + col] = make_float2(a0, a1);
            *(float2*)&C[(size_t)r1 * DMODEL + col] = make_float2(a2, a3);
        }
    }
}

__global__ void __launch_bounds__(256, 2) qkv_kernel(const int* __restrict__ pos)
{
    const int z = blockIdx.z;
    const float* W = g_w4 + (size_t)z * DMODEL * DMODEL;
    float* dst = (z == 0) ? g_q : (z == 1) ? g_k : g_v;
    gemm_tc(g_xc, W, dst, z < 2 ? 1 : 0, pos, 1);
}

__global__ void __launch_bounds__(256, 2) proj_kernel(float* __restrict__ out)
{
    gemm_tc(g_attn, g_w4 + (size_t)3 * DMODEL * DMODEL, out, 0, (const int*)0, 0);
}

// ---------------------------------------------------------------------------
// Causal flash attention, tf32 warp MMA.
// 3-stage cp.async pipeline, ONE __syncthreads per key tile.
// 256 threads / 128 queries per q-tile, key tiles of 64; CTA does the
// q-tile pair (p, NQT-1-p) -> uniform 34 tile-units per CTA.
// Diagonal tiles bound the nf (QK) and s (PV) loops by the causal limit.
// ---------------------------------------------------------------------------
#define ATTN_STAGE 35840
#define ATTN_DSM   (3 * ATTN_STAGE)

__device__ __forceinline__ void attn_qtile(int qt, int b, int h,
                                           char* asm_s, uint32_t sb)
{
    const int tid = threadIdx.x, warp = tid >> 5, lane = tid & 31;
    const int g = lane >> 2, qd = lane & 3;

    const int r0 = qt * 128 + warp * 16 + g;
    const int r1 = r0 + 8;
    const int wrow_lo = qt * 128 + warp * 16;
    const int wrow_hi = wrow_lo + 15;

    uint32_t qa[8][4];
    const float* q0p = g_q + ((size_t)(b * SEQ + r0)) * DMODEL + h * DHEAD;
    const float* q1p = g_q + ((size_t)(b * SEQ + r1)) * DMODEL + h * DHEAD;
#pragma unroll
    for (int s = 0; s < 8; s++) {
        qa[s][0] = __float_as_uint(q0p[s * 8 + qd]     * 0.125f);
        qa[s][1] = __float_as_uint(q1p[s * 8 + qd]     * 0.125f);
        qa[s][2] = __float_as_uint(q0p[s * 8 + qd + 4] * 0.125f);
        qa[s][3] = __float_as_uint(q1p[s * 8 + qd + 4] * 0.125f);
    }

    float oacc[8][4];
#pragma unroll
    for (int i = 0; i < 8; i++)
#pragma unroll
        for (int k = 0; k < 4; k++) oacc[i][k] = 0.0f;
    float m0 = -1e30f, m1 = -1e30f, l0 = 0.0f, l1 = 0.0f;

    const int lrow = tid >> 2;
    const int lc   = (tid & 3) * 16;
    const int ntiles = 2 * qt + 2;
    const size_t gstep = (size_t)(b * SEQ + lrow) * DMODEL + h * DHEAD + lc;

    auto issue_tile = [&](int t) {
        const float* kp = g_k + gstep + (size_t)t * 64 * DMODEL;
        const float* vp = g_v + gstep + (size_t)t * 64 * DMODEL;
        const uint32_t st = sb + (uint32_t)(t % 3) * ATTN_STAGE;
        const uint32_t ka = st + (uint32_t)(lrow * 68 + lc) * 4u;
        const uint32_t va = st + 17408u + (uint32_t)(lrow * 72 + lc) * 4u;
#pragma unroll
        for (int i = 0; i < 4; i++) {
            cp16(ka + i * 16, kp + i * 4);
            cp16(va + i * 16, vp + i * 4);
        }
    };

    issue_tile(0);
    cp_commit();

    for (int kt = 0; kt < ntiles; kt++) {
        if (kt + 1 < ntiles) issue_tile(kt + 1);   // stage (kt+1)%3 == (kt-2)%3: drained
        cp_commit();
        cp_wait1();
        __syncthreads();

        const int kbase = kt * 64;
        if (kbase <= wrow_hi) {
            const uint32_t* Ks = (const uint32_t*)(asm_s + (kt % 3) * ATTN_STAGE);
            const uint32_t* Vs = (const uint32_t*)(asm_s + (kt % 3) * ATTN_STAGE + 17408);
            const bool needmask = (kbase + 63 > wrow_lo);
            const int lim = needmask ? ((wrow_hi - kbase) >> 3) : 7;

            float sacc[8][4];
#pragma unroll
            for (int nf = 0; nf < 8; nf++) {
                if (nf <= lim) {
                    sacc[nf][0] = sacc[nf][1] = sacc[nf][2] = sacc[nf][3] = 0.0f;
#pragma unroll
                    for (int s = 0; s < 8; s++) {
                        uint32_t bf[2];
                        const uint32_t* kb = &Ks[(nf * 8 + g) * 68 + s * 8 + qd];
                        bf[0] = kb[0];
                        bf[1] = kb[4];
                        mma_tf32(sacc[nf], qa[s], bf);
                    }
                } else {
                    sacc[nf][0] = sacc[nf][1] = sacc[nf][2] = sacc[nf][3] = -1e30f;
                }
            }

            if (needmask) {
#pragma unroll
                for (int nf = 0; nf < 8; nf++) {
                    const int c0 = kbase + nf * 8 + 2 * qd;
                    if (c0 > r0)     sacc[nf][0] = -1e30f;
                    if (c0 + 1 > r0) sacc[nf][1] = -1e30f;
                    if (c0 > r1)     sacc[nf][2] = -1e30f;
                    if (c0 + 1 > r1) sacc[nf][3] = -1e30f;
                }
            }

            float mx0 = -1e30f, mx1 = -1e30f;
#pragma unroll
            for (int nf = 0; nf < 8; nf++) {
                mx0 = fmaxf(mx0, fmaxf(sacc[nf][0], sacc[nf][1]));
                mx1 = fmaxf(mx1, fmaxf(sacc[nf][2], sacc[nf][3]));
            }
            mx0 = fmaxf(mx0, __shfl_xor_sync(0xffffffffu, mx0, 1));
            mx0 = fmaxf(mx0, __shfl_xor_sync(0xffffffffu, mx0, 2));
            mx1 = fmaxf(mx1, __shfl_xor_sync(0xffffffffu, mx1, 1));
            mx1 = fmaxf(mx1, __shfl_xor_sync(0xffffffffu, mx1, 2));

            const float mn0 = fmaxf(m0, mx0), mn1 = fmaxf(m1, mx1);
            const float cr0 = __expf(m0 - mn0), cr1 = __expf(m1 - mn1);
            float sum0 = 0.0f, sum1 = 0.0f;
#pragma unroll
            for (int nf = 0; nf < 8; nf++) {
                sacc[nf][0] = __expf(sacc[nf][0] - mn0);
                sacc[nf][1] = __expf(sacc[nf][1] - mn0);
                sacc[nf][2] = __expf(sacc[nf][2] - mn1);
                sacc[nf][3] = __expf(sacc[nf][3] - mn1);
                sum0 += sacc[nf][0] + sacc[nf][1];
                sum1 += sacc[nf][2] + sacc[nf][3];
            }
            sum0 += __shfl_xor_sync(0xffffffffu, sum0, 1);
            sum0 += __shfl_xor_sync(0xffffffffu, sum0, 2);
            sum1 += __shfl_xor_sync(0xffffffffu, sum1, 1);
            sum1 += __shfl_xor_sync(0xffffffffu, sum1, 2);
            l0 = l0 * cr0 + sum0;
            l1 = l1 * cr1 + sum1;
            m0 = mn0; m1 = mn1;
#pragma unroll
            for (int nf = 0; nf < 8; nf++) {
                oacc[nf][0] *= cr0; oacc[nf][1] *= cr0;
                oacc[nf][2] *= cr1; oacc[nf][3] *= cr1;
            }

            const int src0 = (lane & 0x1c) | (qd >> 1);
            const int src1 = src0 + 2;
            const bool odd = (qd & 1);
#pragma unroll
            for (int s = 0; s < 8; s++) {
                if (s > lim) continue;
                const float A0 = sacc[s][0], A1 = sacc[s][1];
                const float A2 = sacc[s][2], A3 = sacc[s][3];
                const float x0 = __shfl_sync(0xffffffffu, A0, src0);
                const float x1 = __shfl_sync(0xffffffffu, A1, src0);
                const float y0 = __shfl_sync(0xffffffffu, A2, src0);
                const float y1 = __shfl_sync(0xffffffffu, A3, src0);
                const float z0 = __shfl_sync(0xffffffffu, A0, src1);
                const float z1 = __shfl_sync(0xffffffffu, A1, src1);
                const float w0 = __shfl_sync(0xffffffffu, A2, src1);
                const float w1 = __shfl_sync(0xffffffffu, A3, src1);
                uint32_t af[4];
                af[0] = f2tf(odd ? x1 : x0);
                af[1] = f2tf(odd ? y1 : y0);
                af[2] = f2tf(odd ? z1 : z0);
                af[3] = f2tf(odd ? w1 : w0);
#pragma unroll
                for (int nf = 0; nf < 8; nf++) {
                    uint32_t bf[2];
                    const uint32_t* vb = &Vs[(s * 8 + qd) * 72 + nf * 8 + g];
                    bf[0] = vb[0];
                    bf[1] = vb[4 * 72];
                    mma_tf32(oacc[nf], af, bf);
                }
            }
        }
    }

    cp_wait0();   // drain before the next q-tile reuses stages

    const float il0 = 1.0f / l0, il1 = 1.0f / l1;
    float* o0 = g_attn + ((size_t)(b * SEQ + r0)) * DMODEL + h * DHEAD;
    float* o1 = g_attn + ((size_t)(b * SEQ + r1)) * DMODEL + h * DHEAD;
#pragma unroll
    for (int nf = 0; nf < 8; nf++) {
        const int c = nf * 8 + 2 * qd;
        float2 v0, v1;
        v0.x = __uint_as_float(f2tf(oacc[nf][0] * il0));
        v0.y = __uint_as_float(f2tf(oacc[nf][1] * il0));
        v1.x = __uint_as_float(f2tf(oacc[nf][2] * il1));
        v1.y = __uint_as_float(f2tf(oacc[nf][3] * il1));
        *(float2*)&o0[c] = v0;
        *(float2*)&o1[c] = v1;
    }
}

__global__ void __launch_bounds__(256) attn_kernel()
{
    extern __shared__ char asm_s[];
    const uint32_t sb = smem_u32(asm_s);
    const int b = blockIdx.z, h = blockIdx.y;

    attn_qtile(NQT - 1 - blockIdx.x, b, h, asm_s, sb);   // heavy tile
    __syncthreads();
    attn_qtile(blockIdx.x, b, h, asm_s, sb);             // light tile
}

// ---------------------------------------------------------------------------
extern "C" void kernel_launch(void* const* d_in, const int* in_sizes, int n_in,
                              void* d_out, int out_size)
{
    const float* X  = (const float*)d_in[0];
    const float* Wq = (const float*)d_in[1];
    const float* Wk = (const float*)d_in[2];
    const float* Wv = (const float*)d_in[3];
    const float* Wo = (const float*)d_in[4];
    const int*  pos = (const int*)d_in[5];

    cudaFuncSetAttribute(qkv_kernel,  cudaFuncAttributeMaxDynamicSharedMemorySize, GEMM_DSM);
    cudaFuncSetAttribute(proj_kernel, cudaFuncAttributeMaxDynamicSharedMemorySize, GEMM_DSM);
    cudaFuncSetAttribute(attn_kernel, cudaFuncAttributeMaxDynamicSharedMemorySize, ATTN_DSM);

    cvt_kernel<<<dim3(4096, 5), 256>>>(X, Wq, Wk, Wv, Wo);
    qkv_kernel<<<dim3(DMODEL / 128, BT / 128, 3), 256, GEMM_DSM>>>(pos);
    attn_kernel<<<dim3(NQT / 2, NHEAD, BATCH), 256, ATTN_DSM>>>();
    proj_kernel<<<dim3(DMODEL / 128, BT / 128, 1), 256, GEMM_DSM>>>((float*)d_out);
}

// round 10
// speedup vs baseline: 1.1754x; 1.1316x over previous
#include <cuda_runtime.h>
#include <cuda_bf16.h>
#include <math.h>
#include <stdint.h>

#define BATCH   2
#define SEQ     2048
#define DMODEL  1024
#define NHEAD   16
#define DHEAD   64
#define BT      (BATCH * SEQ)
#define NQT     (SEQ / 128)

// Scratch (device globals). All hold tf32-rounded fp32.
__device__ float g_q[BT * DMODEL];
__device__ float g_k[BT * DMODEL];
__device__ float g_v[BT * DMODEL];
__device__ float g_attn[BT * DMODEL];
__device__ float g_xc[BT * DMODEL];
__device__ float g_w4[4 * DMODEL * DMODEL];

__device__ __forceinline__ uint32_t f2tf(float f) {
    uint32_t u;
    asm("cvt.rna.tf32.f32 %0, %1;" : "=r"(u) : "f"(f));
    return u;
}

__device__ __forceinline__ uint32_t smem_u32(const void* p) {
    uint32_t a;
    asm("{ .reg .u64 t; cvta.to.shared.u64 t, %1; cvt.u32.u64 %0, t; }" : "=r"(a) : "l"(p));
    return a;
}

__device__ __forceinline__ void mma_tf32(float c[4], const uint32_t a[4], const uint32_t b[2]) {
    asm volatile(
        "mma.sync.aligned.m16n8k8.row.col.f32.tf32.tf32.f32 "
        "{%0,%1,%2,%3}, {%4,%5,%6,%7}, {%8,%9}, {%0,%1,%2,%3};"
        : "+f"(c[0]), "+f"(c[1]), "+f"(c[2]), "+f"(c[3])
        : "r"(a[0]), "r"(a[1]), "r"(a[2]), "r"(a[3]), "r"(b[0]), "r"(b[1]));
}

__device__ __forceinline__ void cp16(uint32_t dst, const void* src) {
    asm volatile("cp.async.cg.shared.global [%0], [%1], 16;" :: "r"(dst), "l"(src));
}
__device__ __forceinline__ void cp_commit() {
    asm volatile("cp.async.commit_group;");
}
__device__ __forceinline__ void cp_wait2() {
    asm volatile("cp.async.wait_group 2;");
}
__device__ __forceinline__ void cp_wait1() {
    asm volatile("cp.async.wait_group 1;");
}

// ---------------------------------------------------------------------------
// Prepass: round X and the four weights to tf32 once.
// ---------------------------------------------------------------------------
__global__ void cvt_kernel(const float* __restrict__ X,
                           const float* __restrict__ Wq,
                           const float* __restrict__ Wk,
                           const float* __restrict__ Wv,
                           const float* __restrict__ Wo)
{
    const int y = blockIdx.y;
    const float* src;
    float* dst;
    int n;
    if (y == 0)      { src = X;  dst = g_xc;                          n = BT * DMODEL; }
    else             { src = (y == 1) ? Wq : (y == 2) ? Wk : (y == 3) ? Wv : Wo;
                       dst = g_w4 + (size_t)(y - 1) * DMODEL * DMODEL; n = DMODEL * DMODEL; }
    const int i = (blockIdx.x * 256 + threadIdx.x) * 4;
    if (i < n) {
        float4 v = *(const float4*)(src + i);
        uint4 u;
        u.x = f2tf(v.x); u.y = f2tf(v.y); u.z = f2tf(v.z); u.w = f2tf(v.w);
        *(uint4*)(dst + i) = u;
    }
}

// ---------------------------------------------------------------------------
// TF32 tensor-core GEMM (best measured config): C[m,n] = sum_k A[m,k]*B[n,k]
// Block 128x128, 8 warps (2x4), warp tile 64x32, K-stage 16, 4-stage cp.async,
// one __syncthreads per k-step. Smem row stride 20 words (conflict-free).
// ---------------------------------------------------------------------------
#define GEMM_DSM 81920

__device__ __forceinline__ void gemm_tc(const float* __restrict__ A,
                                        const float* __restrict__ B,
                                        float* __restrict__ C,
                                        int rope, const int* __restrict__ pos,
                                        int tfout)
{
    extern __shared__ float dsm[];
    const uint32_t sb = smem_u32(dsm);

    const int tid  = threadIdx.x;
    const int warp = tid >> 5, lane = tid & 31;
    const int wm = warp >> 2, wn = warp & 3;
    const int g  = lane >> 2, qd = lane & 3;
    const int mbase = blockIdx.y * 128;
    const int nbase = blockIdx.x * 128;

    const int r  = tid >> 1;
    const int cq = (tid & 1) * 2;
    const float* Arow = A + (size_t)(mbase + r) * DMODEL + cq * 4;
    const float* Brow = B + (size_t)(nbase + r) * DMODEL + cq * 4;
    const uint32_t dOff = (uint32_t)r * 80u + (uint32_t)cq * 16u;

    float acc[4][4][4];
#pragma unroll
    for (int i = 0; i < 4; i++)
#pragma unroll
        for (int j = 0; j < 4; j++)
#pragma unroll
            for (int k = 0; k < 4; k++) acc[i][j][k] = 0.0f;

#pragma unroll
    for (int s = 0; s < 3; s++) {
        const uint32_t da = sb + (uint32_t)s * 10240u + dOff;
        const uint32_t db = da + 40960u;
        cp16(da,      Arow + s * 16);
        cp16(da + 16, Arow + s * 16 + 4);
        cp16(db,      Brow + s * 16);
        cp16(db + 16, Brow + s * 16 + 4);
        cp_commit();
    }

    const int NK = DMODEL / 16;   // 64
    for (int kt = 0; kt < NK; kt++) {
        cp_wait2();
        __syncthreads();

        if (kt + 3 < NK) {
            const int s = kt + 3;
            const uint32_t da = sb + (uint32_t)(s & 3) * 10240u + dOff;
            const uint32_t db = da + 40960u;
            cp16(da,      Arow + s * 16);
            cp16(da + 16, Arow + s * 16 + 4);
            cp16(db,      Brow + s * 16);
            cp16(db + 16, Brow + s * 16 + 4);
        }
        cp_commit();

        const uint32_t* Ast = (const uint32_t*)(dsm + (kt & 3) * 2560);
        const uint32_t* Bst = (const uint32_t*)(dsm + 10240 + (kt & 3) * 2560);
#pragma unroll
        for (int ks = 0; ks < 2; ks++) {
            uint32_t af[4][4], bf[4][2];
#pragma unroll
            for (int mf = 0; mf < 4; mf++) {
                const uint32_t* p = &Ast[(wm * 64 + mf * 16 + g) * 20 + ks * 8 + qd];
                af[mf][0] = p[0];
                af[mf][1] = p[160];
                af[mf][2] = p[4];
                af[mf][3] = p[164];
            }
#pragma unroll
            for (int nf = 0; nf < 4; nf++) {
                const uint32_t* p = &Bst[(wn * 32 + nf * 8 + g) * 20 + ks * 8 + qd];
                bf[nf][0] = p[0];
                bf[nf][1] = p[4];
            }
#pragma unroll
            for (int mf = 0; mf < 4; mf++)
#pragma unroll
                for (int nf = 0; nf < 4; nf++)
                    mma_tf32(acc[mf][nf], af[mf], bf[nf]);
        }
    }

    // epilogue (optional fused RoPE; optional tf32 rounding of stores)
#pragma unroll
    for (int mf = 0; mf < 4; mf++) {
        const int r0 = mbase + wm * 64 + mf * 16 + g;
        const int r1 = r0 + 8;
        float p0 = 0.0f, p1 = 0.0f;
        if (rope) {
            p0 = (float)pos[r0 & (SEQ - 1)];
            p1 = (float)pos[r1 & (SEQ - 1)];
        }
#pragma unroll
        for (int nf = 0; nf < 4; nf++) {
            const int col = nbase + wn * 32 + nf * 8 + 2 * qd;
            float a0 = acc[mf][nf][0], a1 = acc[mf][nf][1];
            float a2 = acc[mf][nf][2], a3 = acc[mf][nf][3];
            if (rope) {
                const int j = (col >> 1) & 31;
                const float inv = exp2f((float)j * -0.41524101186092029f);
                float s0, c0, s1, c1;
                sincosf(p0 * inv, &s0, &c0);
                sincosf(p1 * inv, &s1, &c1);
                float n0 = a0 * c0 - a1 * s0;
                float n1 = a0 * s0 + a1 * c0;
                float n2 = a2 * c1 - a3 * s1;
                float n3 = a2 * s1 + a3 * c1;
                a0 = n0; a1 = n1; a2 = n2; a3 = n3;
            }
            if (tfout) {
                a0 = __uint_as_float(f2tf(a0));
                a1 = __uint_as_float(f2tf(a1));
                a2 = __uint_as_float(f2tf(a2));
                a3 = __uint_as_float(f2tf(a3));
            }
            *(float2*)&C[(size_t)r0 * DMODEL + col] = make_float2(a0, a1);
            *(float2*)&C[(size_t)r1 * DMODEL + col] = make_float2(a2, a3);
        }
    }
}

__global__ void __launch_bounds__(256, 2) qkv_kernel(const int* __restrict__ pos)
{
    const int z = blockIdx.z;
    const float* W = g_w4 + (size_t)z * DMODEL * DMODEL;
    float* dst = (z == 0) ? g_q : (z == 1) ? g_k : g_v;
    gemm_tc(g_xc, W, dst, z < 2 ? 1 : 0, pos, 1);
}

__global__ void __launch_bounds__(256, 2) proj_kernel(float* __restrict__ out)
{
    gemm_tc(g_attn, g_w4 + (size_t)3 * DMODEL * DMODEL, out, 0, (const int*)0, 0);
}

// ---------------------------------------------------------------------------
// Causal flash attention, tf32 warp MMA (R7-measured-best inner structure).
// 2-stage cp.async pipeline, two __syncthreads per key tile, full diagonal
// compute (no data-dependent loop bounds). Q scaled by 0.125*log2(e) so the
// softmax uses bare exp2f (EX2, no FMUL).
// ---------------------------------------------------------------------------
#define ATTN_STAGE 35840
#define ATTN_DSM   (2 * ATTN_STAGE)
#define QSCALE     0.18033688011112042f   // 0.125 * log2(e)
#define NINF       -1e30f

__device__ __forceinline__ void attn_qtile(int qt, int b, int h,
                                           char* asm_s, uint32_t sb)
{
    const int tid = threadIdx.x, warp = tid >> 5, lane = tid & 31;
    const int g = lane >> 2, qd = lane & 3;

    const int r0 = qt * 128 + warp * 16 + g;
    const int r1 = r0 + 8;
    const int wrow_lo = qt * 128 + warp * 16;
    const int wrow_hi = wrow_lo + 15;

    uint32_t qa[8][4];
    const float* q0p = g_q + ((size_t)(b * SEQ + r0)) * DMODEL + h * DHEAD;
    const float* q1p = g_q + ((size_t)(b * SEQ + r1)) * DMODEL + h * DHEAD;
#pragma unroll
    for (int s = 0; s < 8; s++) {
        qa[s][0] = f2tf(q0p[s * 8 + qd]     * QSCALE);
        qa[s][1] = f2tf(q1p[s * 8 + qd]     * QSCALE);
        qa[s][2] = f2tf(q0p[s * 8 + qd + 4] * QSCALE);
        qa[s][3] = f2tf(q1p[s * 8 + qd + 4] * QSCALE);
    }

    float oacc[8][4];
#pragma unroll
    for (int i = 0; i < 8; i++)
#pragma unroll
        for (int k = 0; k < 4; k++) oacc[i][k] = 0.0f;
    float m0 = NINF, m1 = NINF, l0 = 0.0f, l1 = 0.0f;

    const int lrow = tid >> 2;
    const int lc   = (tid & 3) * 16;
    const int ntiles = 2 * qt + 2;
    const size_t gstep = (size_t)(b * SEQ + lrow) * DMODEL + h * DHEAD + lc;

    auto issue_tile = [&](int t) {
        const float* kp = g_k + gstep + (size_t)t * 64 * DMODEL;
        const float* vp = g_v + gstep + (size_t)t * 64 * DMODEL;
        const uint32_t st = sb + (uint32_t)(t & 1) * ATTN_STAGE;
        const uint32_t ka = st + (uint32_t)(lrow * 68 + lc) * 4u;
        const uint32_t va = st + 17408u + (uint32_t)(lrow * 72 + lc) * 4u;
#pragma unroll
        for (int i = 0; i < 4; i++) {
            cp16(ka + i * 16, kp + i * 4);
            cp16(va + i * 16, vp + i * 4);
        }
    };

    issue_tile(0);
    cp_commit();

    for (int kt = 0; kt < ntiles; kt++) {
        if (kt + 1 < ntiles) issue_tile(kt + 1);
        cp_commit();
        cp_wait1();
        __syncthreads();

        const int kbase = kt * 64;
        if (kbase <= wrow_hi) {
            const uint32_t* Ks = (const uint32_t*)(asm_s + (kt & 1) * ATTN_STAGE);
            const uint32_t* Vs = (const uint32_t*)(asm_s + (kt & 1) * ATTN_STAGE + 17408);
            const bool needmask = (kbase + 63 > wrow_lo);

            float sacc[8][4];
#pragma unroll
            for (int nf = 0; nf < 8; nf++) {
                sacc[nf][0] = sacc[nf][1] = sacc[nf][2] = sacc[nf][3] = 0.0f;
#pragma unroll
                for (int s = 0; s < 8; s++) {
                    uint32_t bf[2];
                    const uint32_t* kb = &Ks[(nf * 8 + g) * 68 + s * 8 + qd];
                    bf[0] = kb[0];
                    bf[1] = kb[4];
                    mma_tf32(sacc[nf], qa[s], bf);
                }
            }

            if (needmask) {
#pragma unroll
                for (int nf = 0; nf < 8; nf++) {
                    const int c0 = kbase + nf * 8 + 2 * qd;
                    if (c0 > r0)     sacc[nf][0] = NINF;
                    if (c0 + 1 > r0) sacc[nf][1] = NINF;
                    if (c0 > r1)     sacc[nf][2] = NINF;
                    if (c0 + 1 > r1) sacc[nf][3] = NINF;
                }
            }

            float mx0 = NINF, mx1 = NINF;
#pragma unroll
            for (int nf = 0; nf < 8; nf++) {
                mx0 = fmaxf(mx0, fmaxf(sacc[nf][0], sacc[nf][1]));
                mx1 = fmaxf(mx1, fmaxf(sacc[nf][2], sacc[nf][3]));
            }
            mx0 = fmaxf(mx0, __shfl_xor_sync(0xffffffffu, mx0, 1));
            mx0 = fmaxf(mx0, __shfl_xor_sync(0xffffffffu, mx0, 2));
            mx1 = fmaxf(mx1, __shfl_xor_sync(0xffffffffu, mx1, 1));
            mx1 = fmaxf(mx1, __shfl_xor_sync(0xffffffffu, mx1, 2));

            const float mn0 = fmaxf(m0, mx0), mn1 = fmaxf(m1, mx1);
            const float cr0 = exp2f(m0 - mn0), cr1 = exp2f(m1 - mn1);
            float sum0 = 0.0f, sum1 = 0.0f;
#pragma unroll
            for (int nf = 0; nf < 8; nf++) {
                sacc[nf][0] = exp2f(sacc[nf][0] - mn0);
                sacc[nf][1] = exp2f(sacc[nf][1] - mn0);
                sacc[nf][2] = exp2f(sacc[nf][2] - mn1);
                sacc[nf][3] = exp2f(sacc[nf][3] - mn1);
                sum0 += sacc[nf][0] + sacc[nf][1];
                sum1 += sacc[nf][2] + sacc[nf][3];
            }
            sum0 += __shfl_xor_sync(0xffffffffu, sum0, 1);
            sum0 += __shfl_xor_sync(0xffffffffu, sum0, 2);
            sum1 += __shfl_xor_sync(0xffffffffu, sum1, 1);
            sum1 += __shfl_xor_sync(0xffffffffu, sum1, 2);
            l0 = l0 * cr0 + sum0;
            l1 = l1 * cr1 + sum1;
            m0 = mn0; m1 = mn1;
#pragma unroll
            for (int nf = 0; nf < 8; nf++) {
                oacc[nf][0] *= cr0; oacc[nf][1] *= cr0;
                oacc[nf][2] *= cr1; oacc[nf][3] *= cr1;
            }

            const int src0 = (lane & 0x1c) | (qd >> 1);
            const int src1 = src0 + 2;
            const bool odd = (qd & 1);
#pragma unroll
            for (int s = 0; s < 8; s++) {
                const float A0 = sacc[s][0], A1 = sacc[s][1];
                const float A2 = sacc[s][2], A3 = sacc[s][3];
                const float x0 = __shfl_sync(0xffffffffu, A0, src0);
                const float x1 = __shfl_sync(0xffffffffu, A1, src0);
                const float y0 = __shfl_sync(0xffffffffu, A2, src0);
                const float y1 = __shfl_sync(0xffffffffu, A3, src0);
                const float z0 = __shfl_sync(0xffffffffu, A0, src1);
                const float z1 = __shfl_sync(0xffffffffu, A1, src1);
                const float w0 = __shfl_sync(0xffffffffu, A2, src1);
                const float w1 = __shfl_sync(0xffffffffu, A3, src1);
                uint32_t af[4];
                af[0] = f2tf(odd ? x1 : x0);
                af[1] = f2tf(odd ? y1 : y0);
                af[2] = f2tf(odd ? z1 : z0);
                af[3] = f2tf(odd ? w1 : w0);
#pragma unroll
                for (int nf = 0; nf < 8; nf++) {
                    uint32_t bf[2];
                    const uint32_t* vb = &Vs[(s * 8 + qd) * 72 + nf * 8 + g];
                    bf[0] = vb[0];
                    bf[1] = vb[4 * 72];
                    mma_tf32(oacc[nf], af, bf);
                }
            }
        }
        __syncthreads();   // free stage kt&1 before it is refilled at kt+2
    }

    const float il0 = 1.0f / l0, il1 = 1.0f / l1;
    float* o0 = g_attn + ((size_t)(b * SEQ + r0)) * DMODEL + h * DHEAD;
    float* o1 = g_attn + ((size_t)(b * SEQ + r1)) * DMODEL + h * DHEAD;
#pragma unroll
    for (int nf = 0; nf < 8; nf++) {
        const int c = nf * 8 + 2 * qd;
        float2 v0, v1;
        v0.x = __uint_as_float(f2tf(oacc[nf][0] * il0));
        v0.y = __uint_as_float(f2tf(oacc[nf][1] * il0));
        v1.x = __uint_as_float(f2tf(oacc[nf][2] * il1));
        v1.y = __uint_as_float(f2tf(oacc[nf][3] * il1));
        *(float2*)&o0[c] = v0;
        *(float2*)&o1[c] = v1;
    }
}

__global__ void __launch_bounds__(256) attn_kernel()
{
    extern __shared__ char asm_s[];
    const uint32_t sb = smem_u32(asm_s);
    const int b = blockIdx.z, h = blockIdx.y;

    attn_qtile(NQT - 1 - blockIdx.x, b, h, asm_s, sb);   // heavy tile
    __syncthreads();
    attn_qtile(blockIdx.x, b, h, asm_s, sb);             // light tile
}

// ---------------------------------------------------------------------------
extern "C" void kernel_launch(void* const* d_in, const int* in_sizes, int n_in,
                              void* d_out, int out_size)
{
    const float* X  = (const float*)d_in[0];
    const float* Wq = (const float*)d_in[1];
    const float* Wk = (const float*)d_in[2];
    const float* Wv = (const float*)d_in[3];
    const float* Wo = (const float*)d_in[4];
    const int*  pos = (const int*)d_in[5];

    cudaFuncSetAttribute(qkv_kernel,  cudaFuncAttributeMaxDynamicSharedMemorySize, GEMM_DSM);
    cudaFuncSetAttribute(proj_kernel, cudaFuncAttributeMaxDynamicSharedMemorySize, GEMM_DSM);
    cudaFuncSetAttribute(attn_kernel, cudaFuncAttributeMaxDynamicSharedMemorySize, ATTN_DSM);

    cvt_kernel<<<dim3(4096, 5), 256>>>(X, Wq, Wk, Wv, Wo);
    qkv_kernel<<<dim3(DMODEL / 128, BT / 128, 3), 256, GEMM_DSM>>>(pos);
    attn_kernel<<<dim3(NQT / 2, NHEAD, BATCH), 256, ATTN_DSM>>>();
    proj_kernel<<<dim3(DMODEL / 128, BT / 128, 1), 256, GEMM_DSM>>>((float*)d_out);
}

// round 12
// speedup vs baseline: 1.3165x; 1.1200x over previous
#include <cuda_runtime.h>
#include <cuda_bf16.h>
#include <math.h>
#include <stdint.h>

#define BATCH   2
#define SEQ     2048
#define DMODEL  1024
#define NHEAD   16
#define DHEAD   64
#define BT      (BATCH * SEQ)
#define NQT     (SEQ / 128)

// Scratch (device globals). All hold tf32-rounded fp32.
__device__ float g_q[BT * DMODEL];
__device__ float g_k[BT * DMODEL];
__device__ float g_v[BT * DMODEL];
__device__ float g_attn[BT * DMODEL];
__device__ float g_xc[BT * DMODEL];
__device__ float g_w4[4 * DMODEL * DMODEL];

__device__ __forceinline__ uint32_t f2tf(float f) {
    uint32_t u;
    asm("cvt.rna.tf32.f32 %0, %1;" : "=r"(u) : "f"(f));
    return u;
}

__device__ __forceinline__ uint32_t smem_u32(const void* p) {
    uint32_t a;
    asm("{ .reg .u64 t; cvta.to.shared.u64 t, %1; cvt.u32.u64 %0, t; }" : "=r"(a) : "l"(p));
    return a;
}

__device__ __forceinline__ void mma_tf32(float c[4], const uint32_t a[4], const uint32_t b[2]) {
    asm volatile(
        "mma.sync.aligned.m16n8k8.row.col.f32.tf32.tf32.f32 "
        "{%0,%1,%2,%3}, {%4,%5,%6,%7}, {%8,%9}, {%0,%1,%2,%3};"
        : "+f"(c[0]), "+f"(c[1]), "+f"(c[2]), "+f"(c[3])
        : "r"(a[0]), "r"(a[1]), "r"(a[2]), "r"(a[3]), "r"(b[0]), "r"(b[1]));
}

// ldmatrix x4: four 8x8 b16 matrices == four tf32 fragment registers, when each
// smem "matrix row" is 4 consecutive b32 words. Lane l supplies the row address
// for matrix (l>>3), row (l&7). Distribution: lane j <- row j>>2, word j&3.
__device__ __forceinline__ void ldsm4(uint32_t& r0, uint32_t& r1, uint32_t& r2, uint32_t& r3,
                                      uint32_t addr) {
    asm volatile("ldmatrix.sync.aligned.m8n8.x4.shared.b16 {%0,%1,%2,%3}, [%4];"
                 : "=r"(r0), "=r"(r1), "=r"(r2), "=r"(r3) : "r"(addr));
}

__device__ __forceinline__ void cp16(uint32_t dst, const void* src) {
    asm volatile("cp.async.cg.shared.global [%0], [%1], 16;" :: "r"(dst), "l"(src));
}
__device__ __forceinline__ void cp_commit() {
    asm volatile("cp.async.commit_group;");
}
__device__ __forceinline__ void cp_wait2() {
    asm volatile("cp.async.wait_group 2;");
}
__device__ __forceinline__ void cp_wait1() {
    asm volatile("cp.async.wait_group 1;");
}

// ---------------------------------------------------------------------------
// Prepass: round X and the four weights to tf32 once.
// ---------------------------------------------------------------------------
__global__ void cvt_kernel(const float* __restrict__ X,
                           const float* __restrict__ Wq,
                           const float* __restrict__ Wk,
                           const float* __restrict__ Wv,
                           const float* __restrict__ Wo)
{
    const int y = blockIdx.y;
    const float* src;
    float* dst;
    int n;
    if (y == 0)      { src = X;  dst = g_xc;                          n = BT * DMODEL; }
    else             { src = (y == 1) ? Wq : (y == 2) ? Wk : (y == 3) ? Wv : Wo;
                       dst = g_w4 + (size_t)(y - 1) * DMODEL * DMODEL; n = DMODEL * DMODEL; }
    const int i = (blockIdx.x * 256 + threadIdx.x) * 4;
    if (i < n) {
        float4 v = *(const float4*)(src + i);
        uint4 u;
        u.x = f2tf(v.x); u.y = f2tf(v.y); u.z = f2tf(v.z); u.w = f2tf(v.w);
        *(uint4*)(dst + i) = u;
    }
}

// ---------------------------------------------------------------------------
// TF32 tensor-core GEMM: C[m,n] = sum_k A[m,k]*B[n,k]; inputs pre-tf32.
// Block 128x128, 8 warps (2x4), warp tile 64x32, K-stage 16, 4-stage cp.async,
// one __syncthreads per k-step. Smem row stride 20 words.
// Fragment loads via ldmatrix.x4 (6 LDSM per ks-step instead of 24 LDS.32).
// ---------------------------------------------------------------------------
#define GEMM_DSM 81920

__device__ __forceinline__ void gemm_tc(const float* __restrict__ A,
                                        const float* __restrict__ B,
                                        float* __restrict__ C,
                                        int rope, const int* __restrict__ pos,
                                        int tfout)
{
    extern __shared__ float dsm[];
    const uint32_t sb = smem_u32(dsm);

    const int tid  = threadIdx.x;
    const int warp = tid >> 5, lane = tid & 31;
    const int wm = warp >> 2, wn = warp & 3;
    const int g  = lane >> 2, qd = lane & 3;
    const int mbase = blockIdx.y * 128;
    const int nbase = blockIdx.x * 128;

    // ldmatrix per-lane address offsets (bytes), row stride 80B:
    // A x4: m0=(rows+0,col c) m1=(rows+8,c) m2=(rows+0,c+4) m3=(rows+8,c+4)
    const uint32_t laneA = (uint32_t)((lane & 7) + ((lane >> 3) & 1) * 8) * 80u
                         + (uint32_t)(lane >> 4) * 16u;
    // B x4: m0=(nf rows,c) m1=(nf rows,c+4) m2=(nf+1 rows,c) m3=(nf+1 rows,c+4)
    const uint32_t laneB = (uint32_t)((lane & 7) + (lane >> 4) * 8) * 80u
                         + (uint32_t)((lane >> 3) & 1) * 16u;

    const int r  = tid >> 1;
    const int cq = (tid & 1) * 2;
    const float* Arow = A + (size_t)(mbase + r) * DMODEL + cq * 4;
    const float* Brow = B + (size_t)(nbase + r) * DMODEL + cq * 4;
    const uint32_t dOff = (uint32_t)r * 80u + (uint32_t)cq * 16u;

    float acc[4][4][4];
#pragma unroll
    for (int i = 0; i < 4; i++)
#pragma unroll
        for (int j = 0; j < 4; j++)
#pragma unroll
            for (int k = 0; k < 4; k++) acc[i][j][k] = 0.0f;

#pragma unroll
    for (int s = 0; s < 3; s++) {
        const uint32_t da = sb + (uint32_t)s * 10240u + dOff;
        const uint32_t db = da + 40960u;
        cp16(da,      Arow + s * 16);
        cp16(da + 16, Arow + s * 16 + 4);
        cp16(db,      Brow + s * 16);
        cp16(db + 16, Brow + s * 16 + 4);
        cp_commit();
    }

    const int NK = DMODEL / 16;   // 64
    for (int kt = 0; kt < NK; kt++) {
        cp_wait2();
        __syncthreads();

        if (kt + 3 < NK) {
            const int s = kt + 3;
            const uint32_t da = sb + (uint32_t)(s & 3) * 10240u + dOff;
            const uint32_t db = da + 40960u;
            cp16(da,      Arow + s * 16);
            cp16(da + 16, Arow + s * 16 + 4);
            cp16(db,      Brow + s * 16);
            cp16(db + 16, Brow + s * 16 + 4);
        }
        cp_commit();

        const uint32_t aBase = sb + (uint32_t)(kt & 3) * 10240u
                             + (uint32_t)(wm * 64) * 80u + laneA;
        const uint32_t bBase = sb + 40960u + (uint32_t)(kt & 3) * 10240u
                             + (uint32_t)(wn * 32) * 80u + laneB;
#pragma unroll
        for (int ks = 0; ks < 2; ks++) {
            uint32_t af[4][4], bf[4][2];
#pragma unroll
            for (int mf = 0; mf < 4; mf++)
                ldsm4(af[mf][0], af[mf][1], af[mf][2], af[mf][3],
                      aBase + (uint32_t)mf * 1280u + (uint32_t)ks * 32u);
            ldsm4(bf[0][0], bf[0][1], bf[1][0], bf[1][1], bBase + (uint32_t)ks * 32u);
            ldsm4(bf[2][0], bf[2][1], bf[3][0], bf[3][1], bBase + 1280u + (uint32_t)ks * 32u);
#pragma unroll
            for (int mf = 0; mf < 4; mf++)
#pragma unroll
                for (int nf = 0; nf < 4; nf++)
                    mma_tf32(acc[mf][nf], af[mf], bf[nf]);
        }
    }

    // epilogue (optional fused RoPE; optional tf32 rounding of stores)
#pragma unroll
    for (int mf = 0; mf < 4; mf++) {
        const int r0 = mbase + wm * 64 + mf * 16 + g;
        const int r1 = r0 + 8;
        float p0 = 0.0f, p1 = 0.0f;
        if (rope) {
            p0 = (float)pos[r0 & (SEQ - 1)];
            p1 = (float)pos[r1 & (SEQ - 1)];
        }
#pragma unroll
        for (int nf = 0; nf < 4; nf++) {
            const int col = nbase + wn * 32 + nf * 8 + 2 * qd;
            float a0 = acc[mf][nf][0], a1 = acc[mf][nf][1];
            float a2 = acc[mf][nf][2], a3 = acc[mf][nf][3];
            if (rope) {
                const int j = (col >> 1) & 31;
                const float inv = exp2f((float)j * -0.41524101186092029f);
                float s0, c0, s1, c1;
                sincosf(p0 * inv, &s0, &c0);
                sincosf(p1 * inv, &s1, &c1);
                float n0 = a0 * c0 - a1 * s0;
                float n1 = a0 * s0 + a1 * c0;
                float n2 = a2 * c1 - a3 * s1;
                float n3 = a2 * s1 + a3 * c1;
                a0 = n0; a1 = n1; a2 = n2; a3 = n3;
            }
            if (tfout) {
                a0 = __uint_as_float(f2tf(a0));
                a1 = __uint_as_float(f2tf(a1));
                a2 = __uint_as_float(f2tf(a2));
                a3 = __uint_as_float(f2tf(a3));
            }
            *(float2*)&C[(size_t)r0 * DMODEL + col] = make_float2(a0, a1);
            *(float2*)&C[(size_t)r1 * DMODEL + col] = make_float2(a2, a3);
        }
    }
}

__global__ void __launch_bounds__(256, 2) qkv_kernel(const int* __restrict__ pos)
{
    const int z = blockIdx.z;
    const float* W = g_w4 + (size_t)z * DMODEL * DMODEL;
    float* dst = (z == 0) ? g_q : (z == 1) ? g_k : g_v;
    gemm_tc(g_xc, W, dst, z < 2 ? 1 : 0, pos, 1);
}

__global__ void __launch_bounds__(256, 2) proj_kernel(float* __restrict__ out)
{
    gemm_tc(g_attn, g_w4 + (size_t)3 * DMODEL * DMODEL, out, 0, (const int*)0, 0);
}

// ---------------------------------------------------------------------------
// Causal flash attention, tf32 warp MMA (measured-best structure: 2-stage
// pipeline, two barriers/tile, full diagonal compute). exp2-based softmax.
// K fragments via ldmatrix.x4 (32 LDSM vs 128 LDS per warp-tile).
// ---------------------------------------------------------------------------
#define ATTN_STAGE 35840
#define ATTN_DSM   (2 * ATTN_STAGE)
#define QSCALE     0.18033688011112042f   // 0.125 * log2(e)
#define NINF       -1e30f

__device__ __forceinline__ void attn_qtile(int qt, int b, int h,
                                           char* asm_s, uint32_t sb)
{
    const int tid = threadIdx.x, warp = tid >> 5, lane = tid & 31;
    const int g = lane >> 2, qd = lane & 3;

    const int r0 = qt * 128 + warp * 16 + g;
    const int r1 = r0 + 8;
    const int wrow_lo = qt * 128 + warp * 16;
    const int wrow_hi = wrow_lo + 15;

    // ldmatrix lane offset for K tiles (row stride 68 words = 272B):
    // x4 covers one nf (8 K-rows) x 2 s-values: m0=(col s*8) m1=(+4) m2=((s+1)*8) m3=(+4)
    const uint32_t laneK = (uint32_t)(lane & 7) * 272u + (uint32_t)(lane >> 3) * 16u;

    uint32_t qa[8][4];
    const float* q0p = g_q + ((size_t)(b * SEQ + r0)) * DMODEL + h * DHEAD;
    const float* q1p = g_q + ((size_t)(b * SEQ + r1)) * DMODEL + h * DHEAD;
#pragma unroll
    for (int s = 0; s < 8; s++) {
        qa[s][0] = f2tf(q0p[s * 8 + qd]     * QSCALE);
        qa[s][1] = f2tf(q1p[s * 8 + qd]     * QSCALE);
        qa[s][2] = f2tf(q0p[s * 8 + qd + 4] * QSCALE);
        qa[s][3] = f2tf(q1p[s * 8 + qd + 4] * QSCALE);
    }

    float oacc[8][4];
#pragma unroll
    for (int i = 0; i < 8; i++)
#pragma unroll
        for (int k = 0; k < 4; k++) oacc[i][k] = 0.0f;
    float m0 = NINF, m1 = NINF, l0 = 0.0f, l1 = 0.0f;

    const int lrow = tid >> 2;
    const int lc   = (tid & 3) * 16;
    const int ntiles = 2 * qt + 2;
    const size_t gstep = (size_t)(b * SEQ + lrow) * DMODEL + h * DHEAD + lc;

    auto issue_tile = [&](int t) {
        const float* kp = g_k + gstep + (size_t)t * 64 * DMODEL;
        const float* vp = g_v + gstep + (size_t)t * 64 * DMODEL;
        const uint32_t st = sb + (uint32_t)(t & 1) * ATTN_STAGE;
        const uint32_t ka = st + (uint32_t)(lrow * 68 + lc) * 4u;
        const uint32_t va = st + 17408u + (uint32_t)(lrow * 72 + lc) * 4u;
#pragma unroll
        for (int i = 0; i < 4; i++) {
            cp16(ka + i * 16, kp + i * 4);
            cp16(va + i * 16, vp + i * 4);
        }
    };

    issue_tile(0);
    cp_commit();

    for (int kt = 0; kt < ntiles; kt++) {
        if (kt + 1 < ntiles) issue_tile(kt + 1);
        cp_commit();
        cp_wait1();
        __syncthreads();

        const int kbase = kt * 64;
        if (kbase <= wrow_hi) {
            const uint32_t kBase = sb + (uint32_t)(kt & 1) * ATTN_STAGE + laneK;
            const uint32_t* Vs = (const uint32_t*)(asm_s + (kt & 1) * ATTN_STAGE + 17408);
            const bool needmask = (kbase + 63 > wrow_lo);

            float sacc[8][4];
#pragma unroll
            for (int nf = 0; nf < 8; nf++) {
                sacc[nf][0] = sacc[nf][1] = sacc[nf][2] = sacc[nf][3] = 0.0f;
                uint32_t kf[8][2];
                const uint32_t nb = kBase + (uint32_t)nf * 2176u;
                ldsm4(kf[0][0], kf[0][1], kf[1][0], kf[1][1], nb);
                ldsm4(kf[2][0], kf[2][1], kf[3][0], kf[3][1], nb + 64u);
                ldsm4(kf[4][0], kf[4][1], kf[5][0], kf[5][1], nb + 128u);
                ldsm4(kf[6][0], kf[6][1], kf[7][0], kf[7][1], nb + 192u);
#pragma unroll
                for (int s = 0; s < 8; s++)
                    mma_tf32(sacc[nf], qa[s], kf[s]);
            }

            if (needmask) {
#pragma unroll
                for (int nf = 0; nf < 8; nf++) {
                    const int c0 = kbase + nf * 8 + 2 * qd;
                    if (c0 > r0)     sacc[nf][0] = NINF;
                    if (c0 + 1 > r0) sacc[nf][1] = NINF;
                    if (c0 > r1)     sacc[nf][2] = NINF;
                    if (c0 + 1 > r1) sacc[nf][3] = NINF;
                }
            }

            float mx0 = NINF, mx1 = NINF;
#pragma unroll
            for (int nf = 0; nf < 8; nf++) {
                mx0 = fmaxf(mx0, fmaxf(sacc[nf][0], sacc[nf][1]));
                mx1 = fmaxf(mx1, fmaxf(sacc[nf][2], sacc[nf][3]));
            }
            mx0 = fmaxf(mx0, __shfl_xor_sync(0xffffffffu, mx0, 1));
            mx0 = fmaxf(mx0, __shfl_xor_sync(0xffffffffu, mx0, 2));
            mx1 = fmaxf(mx1, __shfl_xor_sync(0xffffffffu, mx1, 1));
            mx1 = fmaxf(mx1, __shfl_xor_sync(0xffffffffu, mx1, 2));

            const float mn0 = fmaxf(m0, mx0), mn1 = fmaxf(m1, mx1);
            const float cr0 = exp2f(m0 - mn0), cr1 = exp2f(m1 - mn1);
            float sum0 = 0.0f, sum1 = 0.0f;
#pragma unroll
            for (int nf = 0; nf < 8; nf++) {
                sacc[nf][0] = exp2f(sacc[nf][0] - mn0);
                sacc[nf][1] = exp2f(sacc[nf][1] - mn0);
                sacc[nf][2] = exp2f(sacc[nf][2] - mn1);
                sacc[nf][3] = exp2f(sacc[nf][3] - mn1);
                sum0 += sacc[nf][0] + sacc[nf][1];
                sum1 += sacc[nf][2] + sacc[nf][3];
            }
            sum0 += __shfl_xor_sync(0xffffffffu, sum0, 1);
            sum0 += __shfl_xor_sync(0xffffffffu, sum0, 2);
            sum1 += __shfl_xor_sync(0xffffffffu, sum1, 1);
            sum1 += __shfl_xor_sync(0xffffffffu, sum1, 2);
            l0 = l0 * cr0 + sum0;
            l1 = l1 * cr1 + sum1;
            m0 = mn0; m1 = mn1;
#pragma unroll
            for (int nf = 0; nf < 8; nf++) {
                oacc[nf][0] *= cr0; oacc[nf][1] *= cr0;
                oacc[nf][2] *= cr1; oacc[nf][3] *= cr1;
            }

            const int src0 = (lane & 0x1c) | (qd >> 1);
            const int src1 = src0 + 2;
            const bool odd = (qd & 1);
#pragma unroll
            for (int s = 0; s < 8; s++) {
                const float A0 = sacc[s][0], A1 = sacc[s][1];
                const float A2 = sacc[s][2], A3 = sacc[s][3];
                const float x0 = __shfl_sync(0xffffffffu, A0, src0);
                const float x1 = __shfl_sync(0xffffffffu, A1, src0);
                const float y0 = __shfl_sync(0xffffffffu, A2, src0);
                const float y1 = __shfl_sync(0xffffffffu, A3, src0);
                const float z0 = __shfl_sync(0xffffffffu, A0, src1);
                const float z1 = __shfl_sync(0xffffffffu, A1, src1);
                const float w0 = __shfl_sync(0xffffffffu, A2, src1);
                const float w1 = __shfl_sync(0xffffffffu, A3, src1);
                uint32_t af[4];
                af[0] = f2tf(odd ? x1 : x0);
                af[1] = f2tf(odd ? y1 : y0);
                af[2] = f2tf(odd ? z1 : z0);
                af[3] = f2tf(odd ? w1 : w0);
#pragma unroll
                for (int nf = 0; nf < 8; nf++) {
                    uint32_t bf[2];
                    const uint32_t* vb = &Vs[(s * 8 + qd) * 72 + nf * 8 + g];
                    bf[0] = vb[0];
                    bf[1] = vb[4 * 72];
                    mma_tf32(oacc[nf], af, bf);
                }
            }
        }
        __syncthreads();   // free stage kt&1 before it is refilled at kt+2
    }

    const float il0 = 1.0f / l0, il1 = 1.0f / l1;
    float* o0 = g_attn + ((size_t)(b * SEQ + r0)) * DMODEL + h * DHEAD;
    float* o1 = g_attn + ((size_t)(b * SEQ + r1)) * DMODEL + h * DHEAD;
#pragma unroll
    for (int nf = 0; nf < 8; nf++) {
        const int c = nf * 8 + 2 * qd;
        float2 v0, v1;
        v0.x = __uint_as_float(f2tf(oacc[nf][0] * il0));
        v0.y = __uint_as_float(f2tf(oacc[nf][1] * il0));
        v1.x = __uint_as_float(f2tf(oacc[nf][2] * il1));
        v1.y = __uint_as_float(f2tf(oacc[nf][3] * il1));
        *(float2*)&o0[c] = v0;
        *(float2*)&o1[c] = v1;
    }
}

__global__ void __launch_bounds__(256) attn_kernel()
{
    extern __shared__ char asm_s[];
    const uint32_t sb = smem_u32(asm_s);
    const int b = blockIdx.z, h = blockIdx.y;

    attn_qtile(NQT - 1 - blockIdx.x, b, h, asm_s, sb);   // heavy tile
    __syncthreads();
    attn_qtile(blockIdx.x, b, h, asm_s, sb);             // light tile
}

// ---------------------------------------------------------------------------
extern "C" void kernel_launch(void* const* d_in, const int* in_sizes, int n_in,
                              void* d_out, int out_size)
{
    const float* X  = (const float*)d_in[0];
    const float* Wq = (const float*)d_in[1];
    const float* Wk = (const float*)d_in[2];
    const float* Wv = (const float*)d_in[3];
    const float* Wo = (const float*)d_in[4];
    const int*  pos = (const int*)d_in[5];

    cudaFuncSetAttribute(qkv_kernel,  cudaFuncAttributeMaxDynamicSharedMemorySize, GEMM_DSM);
    cudaFuncSetAttribute(proj_kernel, cudaFuncAttributeMaxDynamicSharedMemorySize, GEMM_DSM);
    cudaFuncSetAttribute(attn_kernel, cudaFuncAttributeMaxDynamicSharedMemorySize, ATTN_DSM);

    cvt_kernel<<<dim3(4096, 5), 256>>>(X, Wq, Wk, Wv, Wo);
    qkv_kernel<<<dim3(DMODEL / 128, BT / 128, 3), 256, GEMM_DSM>>>(pos);
    attn_kernel<<<dim3(NQT / 2, NHEAD, BATCH), 256, ATTN_DSM>>>();
    proj_kernel<<<dim3(DMODEL / 128, BT / 128, 1), 256, GEMM_DSM>>>((float*)d_out);
}

// round 17
// speedup vs baseline: 1.3876x; 1.0540x over previous
#include <cuda_runtime.h>
#include <cuda_bf16.h>
#include <math.h>
#include <stdint.h>

#define BATCH   2
#define SEQ     2048
#define DMODEL  1024
#define NHEAD   16
#define DHEAD   64
#define BT      (BATCH * SEQ)
#define NQT     (SEQ / 128)

// Scratch (device globals). All hold tf32-rounded fp32.
__device__ float g_q[BT * DMODEL];
__device__ float g_k[BT * DMODEL];
__device__ float g_v[BT * DMODEL];
__device__ float g_attn[BT * DMODEL];
__device__ float g_xc[BT * DMODEL];
__device__ float g_w4[4 * DMODEL * DMODEL];

__device__ __forceinline__ uint32_t f2tf(float f) {
    uint32_t u;
    asm("cvt.rna.tf32.f32 %0, %1;" : "=r"(u) : "f"(f));
    return u;
}

__device__ __forceinline__ uint32_t smem_u32(const void* p) {
    uint32_t a;
    asm("{ .reg .u64 t; cvta.to.shared.u64 t, %1; cvt.u32.u64 %0, t; }" : "=r"(a) : "l"(p));
    return a;
}

__device__ __forceinline__ void mma_tf32(float c[4], const uint32_t a[4], const uint32_t b[2]) {
    asm volatile(
        "mma.sync.aligned.m16n8k8.row.col.f32.tf32.tf32.f32 "
        "{%0,%1,%2,%3}, {%4,%5,%6,%7}, {%8,%9}, {%0,%1,%2,%3};"
        : "+f"(c[0]), "+f"(c[1]), "+f"(c[2]), "+f"(c[3])
        : "r"(a[0]), "r"(a[1]), "r"(a[2]), "r"(a[3]), "r"(b[0]), "r"(b[1]));
}

// ldmatrix x4: four 8x8 b16 matrices == four tf32 fragment registers, when each
// smem "matrix row" is 4 consecutive b32 words.
__device__ __forceinline__ void ldsm4(uint32_t& r0, uint32_t& r1, uint32_t& r2, uint32_t& r3,
                                      uint32_t addr) {
    asm volatile("ldmatrix.sync.aligned.m8n8.x4.shared.b16 {%0,%1,%2,%3}, [%4];"
                 : "=r"(r0), "=r"(r1), "=r"(r2), "=r"(r3) : "r"(addr));
}

__device__ __forceinline__ void sts64(uint32_t addr, uint32_t v0, uint32_t v1) {
    asm volatile("st.shared.v2.b32 [%0], {%1,%2};" :: "r"(addr), "r"(v0), "r"(v1));
}

__device__ __forceinline__ void cp16(uint32_t dst, const void* src) {
    asm volatile("cp.async.cg.shared.global [%0], [%1], 16;" :: "r"(dst), "l"(src));
}
__device__ __forceinline__ void cp_commit() {
    asm volatile("cp.async.commit_group;");
}
__device__ __forceinline__ void cp_wait2() {
    asm volatile("cp.async.wait_group 2;");
}
__device__ __forceinline__ void cp_wait1() {
    asm volatile("cp.async.wait_group 1;");
}

// ---------------------------------------------------------------------------
// Prepass: round X and the four weights to tf32 once.
// ---------------------------------------------------------------------------
__global__ void cvt_kernel(const float* __restrict__ X,
                           const float* __restrict__ Wq,
                           const float* __restrict__ Wk,
                           const float* __restrict__ Wv,
                           const float* __restrict__ Wo)
{
    const int y = blockIdx.y;
    const float* src;
    float* dst;
    int n;
    if (y == 0)      { src = X;  dst = g_xc;                          n = BT * DMODEL; }
    else             { src = (y == 1) ? Wq : (y == 2) ? Wk : (y == 3) ? Wv : Wo;
                       dst = g_w4 + (size_t)(y - 1) * DMODEL * DMODEL; n = DMODEL * DMODEL; }
    const int i = (blockIdx.x * 256 + threadIdx.x) * 4;
    if (i < n) {
        float4 v = *(const float4*)(src + i);
        uint4 u;
        u.x = f2tf(v.x); u.y = f2tf(v.y); u.z = f2tf(v.z); u.w = f2tf(v.w);
        *(uint4*)(dst + i) = u;
    }
}

// ---------------------------------------------------------------------------
// TF32 tensor-core GEMM: C[m,n] = sum_k A[m,k]*B[n,k]; inputs pre-tf32.
// Block 128x128, 8 warps (2x4), warp tile 64x32, K-stage 16, 4-stage cp.async,
// one __syncthreads per k-step. Fragment loads via ldmatrix.x4.
// ---------------------------------------------------------------------------
#define GEMM_DSM 81920

__device__ __forceinline__ void gemm_tc(const float* __restrict__ A,
                                        const float* __restrict__ B,
                                        float* __restrict__ C,
                                        int rope, const int* __restrict__ pos,
                                        int tfout)
{
    extern __shared__ float dsm[];
    const uint32_t sb = smem_u32(dsm);

    const int tid  = threadIdx.x;
    const int warp = tid >> 5, lane = tid & 31;
    const int wm = warp >> 2, wn = warp & 3;
    const int g  = lane >> 2, qd = lane & 3;
    const int mbase = blockIdx.y * 128;
    const int nbase = blockIdx.x * 128;

    const uint32_t laneA = (uint32_t)((lane & 7) + ((lane >> 3) & 1) * 8) * 80u
                         + (uint32_t)(lane >> 4) * 16u;
    const uint32_t laneB = (uint32_t)((lane & 7) + (lane >> 4) * 8) * 80u
                         + (uint32_t)((lane >> 3) & 1) * 16u;

    const int r  = tid >> 1;
    const int cq = (tid & 1) * 2;
    const float* Arow = A + (size_t)(mbase + r) * DMODEL + cq * 4;
    const float* Brow = B + (size_t)(nbase + r) * DMODEL + cq * 4;
    const uint32_t dOff = (uint32_t)r * 80u + (uint32_t)cq * 16u;

    float acc[4][4][4];
#pragma unroll
    for (int i = 0; i < 4; i++)
#pragma unroll
        for (int j = 0; j < 4; j++)
#pragma unroll
            for (int k = 0; k < 4; k++) acc[i][j][k] = 0.0f;

#pragma unroll
    for (int s = 0; s < 3; s++) {
        const uint32_t da = sb + (uint32_t)s * 10240u + dOff;
        const uint32_t db = da + 40960u;
        cp16(da,      Arow + s * 16);
        cp16(da + 16, Arow + s * 16 + 4);
        cp16(db,      Brow + s * 16);
        cp16(db + 16, Brow + s * 16 + 4);
        cp_commit();
    }

    const int NK = DMODEL / 16;   // 64
    for (int kt = 0; kt < NK; kt++) {
        cp_wait2();
        __syncthreads();

        if (kt + 3 < NK) {
            const int s = kt + 3;
            const uint32_t da = sb + (uint32_t)(s & 3) * 10240u + dOff;
            const uint32_t db = da + 40960u;
            cp16(da,      Arow + s * 16);
            cp16(da + 16, Arow + s * 16 + 4);
            cp16(db,      Brow + s * 16);
            cp16(db + 16, Brow + s * 16 + 4);
        }
        cp_commit();

        const uint32_t aBase = sb + (uint32_t)(kt & 3) * 10240u
                             + (uint32_t)(wm * 64) * 80u + laneA;
        const uint32_t bBase = sb + 40960u + (uint32_t)(kt & 3) * 10240u
                             + (uint32_t)(wn * 32) * 80u + laneB;
#pragma unroll
        for (int ks = 0; ks < 2; ks++) {
            uint32_t af[4][4], bf[4][2];
#pragma unroll
            for (int mf = 0; mf < 4; mf++)
                ldsm4(af[mf][0], af[mf][1], af[mf][2], af[mf][3],
                      aBase + (uint32_t)mf * 1280u + (uint32_t)ks * 32u);
            ldsm4(bf[0][0], bf[0][1], bf[1][0], bf[1][1], bBase + (uint32_t)ks * 32u);
            ldsm4(bf[2][0], bf[2][1], bf[3][0], bf[3][1], bBase + 1280u + (uint32_t)ks * 32u);
#pragma unroll
            for (int mf = 0; mf < 4; mf++)
#pragma unroll
                for (int nf = 0; nf < 4; nf++)
                    mma_tf32(acc[mf][nf], af[mf], bf[nf]);
        }
    }

    // epilogue (optional fused RoPE; optional tf32 rounding of stores)
#pragma unroll
    for (int mf = 0; mf < 4; mf++) {
        const int r0 = mbase + wm * 64 + mf * 16 + g;
        const int r1 = r0 + 8;
        float p0 = 0.0f, p1 = 0.0f;
        if (rope) {
            p0 = (float)pos[r0 & (SEQ - 1)];
            p1 = (float)pos[r1 & (SEQ - 1)];
        }
#pragma unroll
        for (int nf = 0; nf < 4; nf++) {
            const int col = nbase + wn * 32 + nf * 8 + 2 * qd;
            float a0 = acc[mf][nf][0], a1 = acc[mf][nf][1];
            float a2 = acc[mf][nf][2], a3 = acc[mf][nf][3];
            if (rope) {
                const int j = (col >> 1) & 31;
                const float inv = exp2f((float)j * -0.41524101186092029f);
                float s0, c0, s1, c1;
                sincosf(p0 * inv, &s0, &c0);
                sincosf(p1 * inv, &s1, &c1);
                float n0 = a0 * c0 - a1 * s0;
                float n1 = a0 * s0 + a1 * c0;
                float n2 = a2 * c1 - a3 * s1;
                float n3 = a2 * s1 + a3 * c1;
                a0 = n0; a1 = n1; a2 = n2; a3 = n3;
            }
            if (tfout) {
                a0 = __uint_as_float(f2tf(a0));
                a1 = __uint_as_float(f2tf(a1));
                a2 = __uint_as_float(f2tf(a2));
                a3 = __uint_as_float(f2tf(a3));
            }
            *(float2*)&C[(size_t)r0 * DMODEL + col] = make_float2(a0, a1);
            *(float2*)&C[(size_t)r1 * DMODEL + col] = make_float2(a2, a3);
        }
    }
}

__global__ void __launch_bounds__(256, 2) qkv_kernel(const int* __restrict__ pos)
{
    const int z = blockIdx.z;
    const float* W = g_w4 + (size_t)z * DMODEL * DMODEL;
    float* dst = (z == 0) ? g_q : (z == 1) ? g_k : g_v;
    gemm_tc(g_xc, W, dst, z < 2 ? 1 : 0, pos, 1);
}

__global__ void __launch_bounds__(256, 2) proj_kernel(float* __restrict__ out)
{
    gemm_tc(g_attn, g_w4 + (size_t)3 * DMODEL * DMODEL, out, 0, (const int*)0, 0);
}

// ---------------------------------------------------------------------------
// Causal flash attention, tf32 warp MMA. 2-stage cp.async pipeline, two
// barriers/tile, exp2 softmax, K fragments via ldmatrix.
// P C-frag -> A-frag via per-warp smem buffer + ldmatrix (replaces the
// 64-shuffle register transpose; warp-private, __syncwarp only).
// ---------------------------------------------------------------------------
#define ATTN_STAGE 35840
#define PBUF_WARP  4352                    // 16 rows x 68 words x 4B
#define ATTN_DSM   (2 * ATTN_STAGE + 8 * PBUF_WARP)
#define QSCALE     0.18033688011112042f    // 0.125 * log2(e)
#define NINF       -1e30f

__device__ __forceinline__ void attn_qtile(int qt, int b, int h,
                                           char* asm_s, uint32_t sb)
{
    const int tid = threadIdx.x, warp = tid >> 5, lane = tid & 31;
    const int g = lane >> 2, qd = lane & 3;

    const int r0 = qt * 128 + warp * 16 + g;
    const int r1 = r0 + 8;
    const int wrow_lo = qt * 128 + warp * 16;
    const int wrow_hi = wrow_lo + 15;

    // ldmatrix lane offset for K tiles (row stride 68 words = 272B)
    const uint32_t laneK = (uint32_t)(lane & 7) * 272u + (uint32_t)(lane >> 3) * 16u;
    // per-warp P buffer; ldmatrix A-frag lane offset (row stride 272B)
    const uint32_t pBase = sb + 2u * ATTN_STAGE + (uint32_t)warp * PBUF_WARP;
    const uint32_t laneP = pBase + (uint32_t)(lane & 15) * 272u + (uint32_t)(lane >> 4) * 16u;
    const uint32_t pst0 = pBase + (uint32_t)g * 272u + (uint32_t)(2 * qd) * 4u;
    const uint32_t pst1 = pst0 + 8u * 272u;

    uint32_t qa[8][4];
    const float* q0p = g_q + ((size_t)(b * SEQ + r0)) * DMODEL + h * DHEAD;
    const float* q1p = g_q + ((size_t)(b * SEQ + r1)) * DMODEL + h * DHEAD;
#pragma unroll
    for (int s = 0; s < 8; s++) {
        qa[s][0] = f2tf(q0p[s * 8 + qd]     * QSCALE);
        qa[s][1] = f2tf(q1p[s * 8 + qd]     * QSCALE);
        qa[s][2] = f2tf(q0p[s * 8 + qd + 4] * QSCALE);
        qa[s][3] = f2tf(q1p[s * 8 + qd + 4] * QSCALE);
    }

    float oacc[8][4];
#pragma unroll
    for (int i = 0; i < 8; i++)
#pragma unroll
        for (int k = 0; k < 4; k++) oacc[i][k] = 0.0f;
    float m0 = NINF, m1 = NINF, l0 = 0.0f, l1 = 0.0f;

    const int lrow = tid >> 2;
    const int lc   = (tid & 3) * 16;
    const int ntiles = 2 * qt + 2;
    const size_t gstep = (size_t)(b * SEQ + lrow) * DMODEL + h * DHEAD + lc;

    auto issue_tile = [&](int t) {
        const float* kp = g_k + gstep + (size_t)t * 64 * DMODEL;
        const float* vp = g_v + gstep + (size_t)t * 64 * DMODEL;
        const uint32_t st = sb + (uint32_t)(t & 1) * ATTN_STAGE;
        const uint32_t ka = st + (uint32_t)(lrow * 68 + lc) * 4u;
        const uint32_t va = st + 17408u + (uint32_t)(lrow * 72 + lc) * 4u;
#pragma unroll
        for (int i = 0; i < 4; i++) {
            cp16(ka + i * 16, kp + i * 4);
            cp16(va + i * 16, vp + i * 4);
        }
    };

    issue_tile(0);
    cp_commit();

    for (int kt = 0; kt < ntiles; kt++) {
        if (kt + 1 < ntiles) issue_tile(kt + 1);
        cp_commit();
        cp_wait1();
        __syncthreads();

        const int kbase = kt * 64;
        if (kbase <= wrow_hi) {
            const uint32_t kBase = sb + (uint32_t)(kt & 1) * ATTN_STAGE + laneK;
            const uint32_t* Vs = (const uint32_t*)(asm_s + (kt & 1) * ATTN_STAGE + 17408);
            const bool needmask = (kbase + 63 > wrow_lo);

            float sacc[8][4];
#pragma unroll
            for (int nf = 0; nf < 8; nf++) {
                sacc[nf][0] = sacc[nf][1] = sacc[nf][2] = sacc[nf][3] = 0.0f;
                uint32_t kf[8][2];
                const uint32_t nb = kBase + (uint32_t)nf * 2176u;
                ldsm4(kf[0][0], kf[0][1], kf[1][0], kf[1][1], nb);
                ldsm4(kf[2][0], kf[2][1], kf[3][0], kf[3][1], nb + 64u);
                ldsm4(kf[4][0], kf[4][1], kf[5][0], kf[5][1], nb + 128u);
                ldsm4(kf[6][0], kf[6][1], kf[7][0], kf[7][1], nb + 192u);
#pragma unroll
                for (int s = 0; s < 8; s++)
                    mma_tf32(sacc[nf], qa[s], kf[s]);
            }

            if (needmask) {
#pragma unroll
                for (int nf = 0; nf < 8; nf++) {
                    const int c0 = kbase + nf * 8 + 2 * qd;
                    if (c0 > r0)     sacc[nf][0] = NINF;
                    if (c0 + 1 > r0) sacc[nf][1] = NINF;
                    if (c0 > r1)     sacc[nf][2] = NINF;
                    if (c0 + 1 > r1) sacc[nf][3] = NINF;
                }
            }

            float mx0 = NINF, mx1 = NINF;
#pragma unroll
            for (int nf = 0; nf < 8; nf++) {
                mx0 = fmaxf(mx0, fmaxf(sacc[nf][0], sacc[nf][1]));
                mx1 = fmaxf(mx1, fmaxf(sacc[nf][2], sacc[nf][3]));
            }
            mx0 = fmaxf(mx0, __shfl_xor_sync(0xffffffffu, mx0, 1));
            mx0 = fmaxf(mx0, __shfl_xor_sync(0xffffffffu, mx0, 2));
            mx1 = fmaxf(mx1, __shfl_xor_sync(0xffffffffu, mx1, 1));
            mx1 = fmaxf(mx1, __shfl_xor_sync(0xffffffffu, mx1, 2));

            const float mn0 = fmaxf(m0, mx0), mn1 = fmaxf(m1, mx1);
            const float cr0 = exp2f(m0 - mn0), cr1 = exp2f(m1 - mn1);
            float sum0 = 0.0f, sum1 = 0.0f;
#pragma unroll
            for (int nf = 0; nf < 8; nf++) {
                sacc[nf][0] = exp2f(sacc[nf][0] - mn0);
                sacc[nf][1] = exp2f(sacc[nf][1] - mn0);
                sacc[nf][2] = exp2f(sacc[nf][2] - mn1);
                sacc[nf][3] = exp2f(sacc[nf][3] - mn1);
                sum0 += sacc[nf][0] + sacc[nf][1];
                sum1 += sacc[nf][2] + sacc[nf][3];
            }
            sum0 += __shfl_xor_sync(0xffffffffu, sum0, 1);
            sum0 += __shfl_xor_sync(0xffffffffu, sum0, 2);
            sum1 += __shfl_xor_sync(0xffffffffu, sum1, 1);
            sum1 += __shfl_xor_sync(0xffffffffu, sum1, 2);
            l0 = l0 * cr0 + sum0;
            l1 = l1 * cr1 + sum1;
            m0 = mn0; m1 = mn1;
#pragma unroll
            for (int nf = 0; nf < 8; nf++) {
                oacc[nf][0] *= cr0; oacc[nf][1] *= cr0;
                oacc[nf][2] *= cr1; oacc[nf][3] *= cr1;
            }

            // P transpose via warp-private smem + ldmatrix:
            // store C-frag pairs (STS.64), reload as A-frags.
            __syncwarp();   // prior ldsm reads of this buffer complete
#pragma unroll
            for (int s = 0; s < 8; s++) {
                sts64(pst0 + (uint32_t)s * 32u, f2tf(sacc[s][0]), f2tf(sacc[s][1]));
                sts64(pst1 + (uint32_t)s * 32u, f2tf(sacc[s][2]), f2tf(sacc[s][3]));
            }
            __syncwarp();

#pragma unroll
            for (int s = 0; s < 8; s++) {
                uint32_t af[4];
                ldsm4(af[0], af[1], af[2], af[3], laneP + (uint32_t)s * 32u);
#pragma unroll
                for (int nf = 0; nf < 8; nf++) {
                    uint32_t bf[2];
                    const uint32_t* vb = &Vs[(s * 8 + qd) * 72 + nf * 8 + g];
                    bf[0] = vb[0];
                    bf[1] = vb[4 * 72];
                    mma_tf32(oacc[nf], af, bf);
                }
            }
        }
        __syncthreads();   // free stage kt&1 before it is refilled at kt+2
    }

    const float il0 = 1.0f / l0, il1 = 1.0f / l1;
    float* o0 = g_attn + ((size_t)(b * SEQ + r0)) * DMODEL + h * DHEAD;
    float* o1 = g_attn + ((size_t)(b * SEQ + r1)) * DMODEL + h * DHEAD;
#pragma unroll
    for (int nf = 0; nf < 8; nf++) {
        const int c = nf * 8 + 2 * qd;
        float2 v0, v1;
        v0.x = __uint_as_float(f2tf(oacc[nf][0] * il0));
        v0.y = __uint_as_float(f2tf(oacc[nf][1] * il0));
        v1.x = __uint_as_float(f2tf(oacc[nf][2] * il1));
        v1.y = __uint_as_float(f2tf(oacc[nf][3] * il1));
        *(float2*)&o0[c] = v0;
        *(float2*)&o1[c] = v1;
    }
}

__global__ void __launch_bounds__(256) attn_kernel()
{
    extern __shared__ char asm_s[];
    const uint32_t sb = smem_u32(asm_s);
    const int b = blockIdx.z, h = blockIdx.y;

    attn_qtile(NQT - 1 - blockIdx.x, b, h, asm_s, sb);   // heavy tile
    __syncthreads();
    attn_qtile(blockIdx.x, b, h, asm_s, sb);             // light tile
}

// ---------------------------------------------------------------------------
extern "C" void kernel_launch(void* const* d_in, const int* in_sizes, int n_in,
                              void* d_out, int out_size)
{
    const float* X  = (const float*)d_in[0];
    const float* Wq = (const float*)d_in[1];
    const float* Wk = (const float*)d_in[2];
    const float* Wv = (const float*)d_in[3];
    const float* Wo = (const float*)d_in[4];
    const int*  pos = (const int*)d_in[5];

    cudaFuncSetAttribute(qkv_kernel,  cudaFuncAttributeMaxDynamicSharedMemorySize, GEMM_DSM);
    cudaFuncSetAttribute(proj_kernel, cudaFuncAttributeMaxDynamicSharedMemorySize, GEMM_DSM);
    cudaFuncSetAttribute(attn_kernel, cudaFuncAttributeMaxDynamicSharedMemorySize, ATTN_DSM);

    cvt_kernel<<<dim3(4096, 5), 256>>>(X, Wq, Wk, Wv, Wo);
    qkv_kernel<<<dim3(DMODEL / 128, BT / 128, 3), 256, GEMM_DSM>>>(pos);
    attn_kernel<<<dim3(NQT / 2, NHEAD, BATCH), 256, ATTN_DSM>>>();
    proj_kernel<<<dim3(DMODEL / 128, BT / 128, 1), 256, GEMM_DSM>>>((float*)d_out);
}